// round 2
// baseline (speedup 1.0000x reference)
#include <cuda_runtime.h>
#include <math.h>

// Problem constants
#define Bn   2
#define Sn   2048
#define HIDn 2048
#define Hn   16
#define Gn   4
#define Dn   128
#define NTOK (Bn * Sn)      // 4096
#define QDIM (Hn * Dn)      // 2048
#define KVDIM (Gn * Dn)     // 512

// Flash tiling
#define BQ 64
#define BK 64
#define QS 68               // padded stride for transposed smem tiles

// Scratch (allocation-free rule: __device__ globals)
__device__ float g_Q[NTOK * QDIM];
__device__ float g_K[NTOK * KVDIM];
__device__ float g_V[NTOK * KVDIM];
__device__ float g_O[NTOK * QDIM];

// ---------------------------------------------------------------------------
// Shared 128x128x8 SGEMM body, 256 threads, 8x8 microtile.
// C[M,N] = A[M,K] @ B[K,N]; all dims multiples of the tile — no bounds checks.
// ---------------------------------------------------------------------------
__device__ __forceinline__
void gemm_body(const float* __restrict__ A, const float* __restrict__ B,
               float* __restrict__ C, int N, int K, int bx, int by) {
    __shared__ float As[8][128];
    __shared__ float Bs[8][128];
    const int tid = threadIdx.x;

    const int aRow = tid >> 1;            // 0..127
    const int aCol = (tid & 1) << 2;      // 0 or 4
    const int bRow = tid >> 5;            // 0..7
    const int bCol = (tid & 31) << 2;     // 0..124
    const int tr = (tid >> 4) << 3;       // 0..120 step 8
    const int tc = (tid & 15) << 3;

    const float* Aptr = A + (size_t)(by * 128 + aRow) * K + aCol;
    const float* Bptr = B + (size_t)bRow * N + bx * 128 + bCol;

    float acc[8][8];
#pragma unroll
    for (int i = 0; i < 8; i++)
#pragma unroll
        for (int j = 0; j < 8; j++) acc[i][j] = 0.f;

    for (int k0 = 0; k0 < K; k0 += 8) {
        float4 av = *(const float4*)(Aptr + k0);
        As[aCol + 0][aRow] = av.x;
        As[aCol + 1][aRow] = av.y;
        As[aCol + 2][aRow] = av.z;
        As[aCol + 3][aRow] = av.w;
        *(float4*)&Bs[bRow][bCol] = *(const float4*)(Bptr + (size_t)k0 * N);
        __syncthreads();
#pragma unroll
        for (int kk = 0; kk < 8; kk++) {
            float ra[8], rb[8];
#pragma unroll
            for (int i = 0; i < 8; i++) ra[i] = As[kk][tr + i];
#pragma unroll
            for (int j = 0; j < 8; j++) rb[j] = Bs[kk][tc + j];
#pragma unroll
            for (int i = 0; i < 8; i++)
#pragma unroll
                for (int j = 0; j < 8; j++) acc[i][j] += ra[i] * rb[j];
        }
        __syncthreads();
    }
#pragma unroll
    for (int i = 0; i < 8; i++) {
        float* crow = C + (size_t)(by * 128 + tr + i) * N + bx * 128 + tc;
        *(float4*)(crow)     = make_float4(acc[i][0], acc[i][1], acc[i][2], acc[i][3]);
        *(float4*)(crow + 4) = make_float4(acc[i][4], acc[i][5], acc[i][6], acc[i][7]);
    }
}

// Fused QKV projection: grid.x = 24 (16 Q tiles + 4 K tiles + 4 V tiles)
__global__ __launch_bounds__(256)
void qkv_gemm(const float* __restrict__ x,
              const float* __restrict__ Wq, const float* __restrict__ Wk,
              const float* __restrict__ Wv,
              float* __restrict__ Q, float* __restrict__ K, float* __restrict__ V) {
    const int bx = blockIdx.x;
    const float* B; float* C; int N; int cx;
    if (bx < 16)      { B = Wq; C = Q; N = QDIM;  cx = bx; }
    else if (bx < 20) { B = Wk; C = K; N = KVDIM; cx = bx - 16; }
    else              { B = Wv; C = V; N = KVDIM; cx = bx - 20; }
    gemm_body(x, B, C, N, HIDn, cx, blockIdx.y);
}

// Output projection (plain)
__global__ __launch_bounds__(256)
void sgemm128(const float* __restrict__ A, const float* __restrict__ B,
              float* __restrict__ C, int N, int K) {
    gemm_body(A, B, C, N, K, blockIdx.x, blockIdx.y);
}

// ---------------------------------------------------------------------------
// RoPE: q'[d]    = q[d]*cos[d]    - q[d+64]*sin[d]       (d < 64)
//       q'[d+64] = q[d+64]*cos[d+64] + q[d]*sin[d+64]
// grid: (NTOK, H+G), 64 threads
// ---------------------------------------------------------------------------
__global__ void rope_kernel(float* __restrict__ Q, float* __restrict__ K,
                            const float* __restrict__ cs, const float* __restrict__ sn) {
    const int t = blockIdx.x;
    const int h = blockIdx.y;
    const int d = threadIdx.x;        // 0..63
    const int s = t & (Sn - 1);
    const float c1 = cs[s * Dn + d],      s1 = sn[s * Dn + d];
    const float c2 = cs[s * Dn + d + 64], s2 = sn[s * Dn + d + 64];
    float* p = (h < Hn) ? (Q + (size_t)t * QDIM + h * Dn)
                        : (K + (size_t)t * KVDIM + (h - Hn) * Dn);
    const float a = p[d], b = p[d + 64];
    p[d]      = a * c1 - b * s1;
    p[d + 64] = b * c2 + a * s2;
}

// ---------------------------------------------------------------------------
// Causal GQA flash attention, fp32. 64 q-rows per CTA, 64-col k tiles, D=128.
// 256 threads; score tile 64x64 with 4x4 microtiles; O accumulated in regs
// (4 rows x 8 cols per thread). Q,K^T stored transposed (stride QS=68) for
// conflict-free float4 inner-loop loads. V reuses the K buffer, loaded
// overlapped with the 64-thread softmax phase.
// ---------------------------------------------------------------------------
__global__ __launch_bounds__(256)
void flash_kernel(const float* __restrict__ Qg, const float* __restrict__ Kg,
                  const float* __restrict__ Vg, float* __restrict__ Og) {
    extern __shared__ float smf[];
    float* Qs      = smf;                    // [Dn][QS] transposed
    float* KV      = smf + Dn * QS;          // K^T [Dn][QS]  OR  V [BK][Dn]
    float* Ps      = smf + 2 * Dn * QS;      // [BQ][QS] scores -> probs
    float* s_scale = Ps + BQ * QS;           // [BQ]
    float* s_l     = s_scale + BQ;           // [BQ]

    const int tid = threadIdx.x;
    const int h = blockIdx.y;
    const int b = blockIdx.z;
    const int qt = (int)gridDim.x - 1 - (int)blockIdx.x;  // longest work first
    const int qb = qt * BQ;
    const int g = h >> 2;                    // GQA group (rep = 4)

    // transpose-load lane mapping: 64B contiguous gmem chunks, 2-way STS conflicts
    const int lr  = tid >> 2;                // row 0..63
    const int lc0 = (tid & 3) << 2;          // base col 0,4,8,12

    // Q tile, pre-scaled by 1/sqrt(D)
    {
        const float* src = Qg + ((size_t)(b * Sn + qb + lr)) * QDIM + h * Dn;
        const float sc = 0.08838834764831845f;  // 1/sqrt(128)
#pragma unroll
        for (int i = 0; i < 8; i++) {
            const int d0 = lc0 + (i << 4);
            float4 v = *(const float4*)(src + d0);
            Qs[(d0 + 0) * QS + lr] = v.x * sc;
            Qs[(d0 + 1) * QS + lr] = v.y * sc;
            Qs[(d0 + 2) * QS + lr] = v.z * sc;
            Qs[(d0 + 3) * QS + lr] = v.w * sc;
        }
    }

    const int tr  = (tid >> 4) << 2;         // score-row base: 0..60 step 4
    const int tc  = (tid & 15) << 2;         // score-col base
    const int tc8 = (tid & 15) << 3;         // O-col base

    float oreg[4][8];
#pragma unroll
    for (int i = 0; i < 4; i++)
#pragma unroll
        for (int c = 0; c < 8; c++) oreg[i][c] = 0.f;

    float m_r = -1e30f, l_r = 0.f;           // owned by tid<64 (row = tid)

    for (int j = 0; j <= qt; j++) {
        // ---- K^T into KV ----
        {
            const float* src = Kg + ((size_t)(b * Sn + j * BK + lr)) * KVDIM + g * Dn;
#pragma unroll
            for (int i = 0; i < 8; i++) {
                const int d0 = lc0 + (i << 4);
                float4 v = *(const float4*)(src + d0);
                KV[(d0 + 0) * QS + lr] = v.x;
                KV[(d0 + 1) * QS + lr] = v.y;
                KV[(d0 + 2) * QS + lr] = v.z;
                KV[(d0 + 3) * QS + lr] = v.w;
            }
        }
        __syncthreads();  // Qs (first iter) + K^T ready; prior PV reads of KV done

        // ---- S = Q K^T (4x4 per thread) ----
        float acc[4][4];
#pragma unroll
        for (int i = 0; i < 4; i++)
#pragma unroll
            for (int c = 0; c < 4; c++) acc[i][c] = 0.f;
#pragma unroll 4
        for (int kk = 0; kk < Dn; kk++) {
            float4 qv = *(const float4*)(Qs + kk * QS + tr);
            float4 kv = *(const float4*)(KV + kk * QS + tc);
            const float qa[4] = {qv.x, qv.y, qv.z, qv.w};
            const float ka[4] = {kv.x, kv.y, kv.z, kv.w};
#pragma unroll
            for (int i = 0; i < 4; i++)
#pragma unroll
                for (int c = 0; c < 4; c++) acc[i][c] += qa[i] * ka[c];
        }

        // ---- causal mask + stage scores ----
#pragma unroll
        for (int i = 0; i < 4; i++) {
            const int grow = qb + tr + i;
#pragma unroll
            for (int c = 0; c < 4; c++) {
                const int gcol = j * BK + tc + c;
                Ps[(tr + i) * QS + tc + c] = (gcol > grow) ? -1e30f : acc[i][c];
            }
        }
        __syncthreads();  // Ps complete; all KV (K^T) reads done

        // ---- V into KV (row-major [BK][Dn]), all threads ----
        {
            const float* src = Vg + ((size_t)(b * Sn + j * BK)) * KVDIM + g * Dn;
#pragma unroll
            for (int i = 0; i < 8; i++) {
                const int idx = (i << 8) + tid;       // 0..2047
                const int r = idx >> 5;
                const int d0 = (idx & 31) << 2;
                *(float4*)(KV + r * Dn + d0) = *(const float4*)(src + (size_t)r * KVDIM + d0);
            }
        }

        // ---- online softmax (one thread per row) ----
        if (tid < BQ) {
            float* row = Ps + tid * QS;
            float rmax = -1e30f;
#pragma unroll 8
            for (int c = 0; c < BK; c++) rmax = fmaxf(rmax, row[c]);
            const float mnew = fmaxf(m_r, rmax);
            const float corr = __expf(m_r - mnew);
            float rsum = 0.f;
#pragma unroll 8
            for (int c = 0; c < BK; c++) {
                const float p = __expf(row[c] - mnew);
                row[c] = p;
                rsum += p;
            }
            l_r = l_r * corr + rsum;
            m_r = mnew;
            s_scale[tid] = corr;
        }
        __syncthreads();  // probs, scale, V all ready

        // ---- rescale O, then O += P @ V ----
        float cr[4];
#pragma unroll
        for (int i = 0; i < 4; i++) cr[i] = s_scale[tr + i];
#pragma unroll
        for (int i = 0; i < 4; i++)
#pragma unroll
            for (int c = 0; c < 8; c++) oreg[i][c] *= cr[i];

#pragma unroll 2
        for (int kk = 0; kk < BK; kk++) {
            const float p0 = Ps[(tr + 0) * QS + kk];
            const float p1 = Ps[(tr + 1) * QS + kk];
            const float p2 = Ps[(tr + 2) * QS + kk];
            const float p3 = Ps[(tr + 3) * QS + kk];
            float4 v0 = *(const float4*)(KV + kk * Dn + tc8);
            float4 v1 = *(const float4*)(KV + kk * Dn + tc8 + 4);
            const float va[8] = {v0.x, v0.y, v0.z, v0.w, v1.x, v1.y, v1.z, v1.w};
#pragma unroll
            for (int c = 0; c < 8; c++) {
                oreg[0][c] += p0 * va[c];
                oreg[1][c] += p1 * va[c];
                oreg[2][c] += p2 * va[c];
                oreg[3][c] += p3 * va[c];
            }
        }
        __syncthreads();  // KV/Ps reads done before next iteration overwrites
    }

    if (tid < BQ) s_l[tid] = l_r;
    __syncthreads();

#pragma unroll
    for (int i = 0; i < 4; i++) {
        const float inv = 1.f / s_l[tr + i];
        float* dst = Og + ((size_t)(b * Sn + qb + tr + i)) * QDIM + h * Dn + tc8;
        *(float4*)(dst)     = make_float4(oreg[i][0] * inv, oreg[i][1] * inv,
                                          oreg[i][2] * inv, oreg[i][3] * inv);
        *(float4*)(dst + 4) = make_float4(oreg[i][4] * inv, oreg[i][5] * inv,
                                          oreg[i][6] * inv, oreg[i][7] * inv);
    }
}

#define FLASH_SMEM ((2 * Dn * QS + BQ * QS + 2 * BQ) * (int)sizeof(float))  // 87552 B

// ---------------------------------------------------------------------------
// Launch: fused x@{Wq,Wk,Wv}  ->  RoPE(Q,K)  ->  flash  ->  O@Wo
// Inputs (metadata order): x, cos, sin, Wq, Wk, Wv, Wo.  Output fp32.
// ---------------------------------------------------------------------------
extern "C" void kernel_launch(void* const* d_in, const int* in_sizes, int n_in,
                              void* d_out, int out_size) {
    const float* x  = (const float*)d_in[0];
    const float* cs = (const float*)d_in[1];
    const float* sn = (const float*)d_in[2];
    const float* Wq = (const float*)d_in[3];
    const float* Wk = (const float*)d_in[4];
    const float* Wv = (const float*)d_in[5];
    const float* Wo = (const float*)d_in[6];
    float* out = (float*)d_out;

    float *Qp = nullptr, *Kp = nullptr, *Vp = nullptr, *Op = nullptr;
    cudaGetSymbolAddress((void**)&Qp, g_Q);
    cudaGetSymbolAddress((void**)&Kp, g_K);
    cudaGetSymbolAddress((void**)&Vp, g_V);
    cudaGetSymbolAddress((void**)&Op, g_O);

    cudaFuncSetAttribute(flash_kernel,
                         cudaFuncAttributeMaxDynamicSharedMemorySize, FLASH_SMEM);

    // Fused QKV projections: 16 Q col-tiles + 4 K + 4 V, 32 row-tiles
    qkv_gemm<<<dim3(24, NTOK / 128), 256>>>(x, Wq, Wk, Wv, Qp, Kp, Vp);

    // RoPE on Q and K
    rope_kernel<<<dim3(NTOK, Hn + Gn), 64>>>(Qp, Kp, cs, sn);

    // Causal GQA flash attention
    flash_kernel<<<dim3(Sn / BQ, Hn, Bn), 256, FLASH_SMEM>>>(Qp, Kp, Vp, Op);

    // Output projection
    sgemm128<<<dim3(HIDn / 128, NTOK / 128), 256>>>(Op, Wo, out, HIDn, QDIM);
}

// round 3
// speedup vs baseline: 1.8005x; 1.8005x over previous
#include <cuda_runtime.h>
#include <math.h>
#include <stdint.h>

// Problem constants
#define Bn   2
#define Sn   2048
#define HIDn 2048
#define Hn   16
#define Gn   4
#define Dn   128
#define NTOK (Bn * Sn)      // 4096
#define QDIM (Hn * Dn)      // 2048
#define KVDIM (Gn * Dn)     // 512

// Flash tiling
#define BQ 64
#define BK 64
#define QS 68

// ---------------------------------------------------------------------------
// Scratch (__device__ globals per allocation-free rule)
// ---------------------------------------------------------------------------
__device__ float g_Q[NTOK * QDIM];
__device__ float g_K[NTOK * KVDIM];
__device__ float g_V[NTOK * KVDIM];
__device__ float g_O[NTOK * QDIM];
// tf32-rounded operand copies
__device__ float g_Xr[NTOK * HIDn];
__device__ float g_Wqr[HIDn * QDIM];
__device__ float g_Wkr[HIDn * KVDIM];
__device__ float g_Wvr[HIDn * KVDIM];
__device__ float g_Wor[QDIM * HIDn];

// ---------------------------------------------------------------------------
// tf32 round-to-nearest helper + elementwise rounding pass
// ---------------------------------------------------------------------------
__device__ __forceinline__ float tf32r(float x) {
    uint32_t u;
    asm("cvt.rna.tf32.f32 %0, %1;" : "=r"(u) : "f"(x));
    return __uint_as_float(u);
}

__global__ void round_tf32_kernel(const float* __restrict__ in,
                                  float* __restrict__ out, int n4) {
    int i = blockIdx.x * blockDim.x + threadIdx.x;
    if (i < n4) {
        float4 v = ((const float4*)in)[i];
        v.x = tf32r(v.x); v.y = tf32r(v.y); v.z = tf32r(v.z); v.w = tf32r(v.w);
        ((float4*)out)[i] = v;
    }
}

// ---------------------------------------------------------------------------
// cp.async helpers
// ---------------------------------------------------------------------------
__device__ __forceinline__ void cp_async16(uint32_t dst, const void* src) {
    asm volatile("cp.async.cg.shared.global [%0], [%1], 16;" :: "r"(dst), "l"(src));
}
__device__ __forceinline__ void cp_commit() {
    asm volatile("cp.async.commit_group;");
}
template <int N>
__device__ __forceinline__ void cp_wait() {
    asm volatile("cp.async.wait_group %0;" :: "n"(N));
}

// ---------------------------------------------------------------------------
// tf32 tensor-core GEMM: C[M,N] = A[M,K] @ B[K,N]
// 128x128 tile, BK=32, 256 threads (8 warps, 2x4), warp tile 64x32,
// mma.sync.m16n8k8.tf32, 2-stage cp.async pipeline.
// A smem [128][36] (row-major), B smem [32][136] (k-major); both strides give
// conflict-free fragment LDS (bank = 4g+c and 8c+g resp., all 32 distinct).
// Inputs MUST already be tf32-rounded (rna), accumulation fp32.
// ---------------------------------------------------------------------------
#define AS_ST 36
#define BS_ST 136
#define A_SZ (128 * AS_ST)            // floats per stage
#define B_SZ (32 * BS_ST)
#define STAGE_SZ (A_SZ + B_SZ)
#define GEMM_SMEM (2 * STAGE_SZ * (int)sizeof(float))   // 71680 B

__device__ __forceinline__
void gemm_tf32_body(const float* __restrict__ A, const float* __restrict__ B,
                    float* __restrict__ C, int N, int K, int bx, int by) {
    extern __shared__ float sm[];
    const int tid  = threadIdx.x;
    const int w    = tid >> 5, lane = tid & 31;
    const int wm   = w >> 2,   wn   = w & 3;     // 2 x 4 warp grid
    const int g    = lane >> 2, c   = lane & 3;  // groupID / threadID_in_group

    const uint32_t smbase = (uint32_t)__cvta_generic_to_shared(sm);

    float d[4][4][4];
#pragma unroll
    for (int i = 0; i < 4; i++)
#pragma unroll
        for (int j = 0; j < 4; j++)
#pragma unroll
            for (int r = 0; r < 4; r++) d[i][j][r] = 0.f;

    const int niter = K / 32;

    // ---- async stage loader ----
    auto issue = [&](int it, int s) {
        const uint32_t sAu = smbase + (uint32_t)(s * STAGE_SZ) * 4u;
        const uint32_t sBu = sAu + (uint32_t)A_SZ * 4u;
        const float* Ag = A + (size_t)(by * 128) * K + it * 32;
        const float* Bg = B + (size_t)(it * 32) * N + bx * 128;
#pragma unroll
        for (int i = 0; i < 4; i++) {
            const int f = i * 256 + tid;
            const int m  = f >> 3, kc = (f & 7) << 2;     // A: 128 rows x 32 cols
            cp_async16(sAu + (uint32_t)(m * AS_ST + kc) * 4u,
                       Ag + (size_t)m * K + kc);
            const int kb = f >> 5, nc = (f & 31) << 2;    // B: 32 rows x 128 cols
            cp_async16(sBu + (uint32_t)(kb * BS_ST + nc) * 4u,
                       Bg + (size_t)kb * N + nc);
        }
        cp_commit();
    };

    issue(0, 0);

    for (int it = 0; it < niter; it++) {
        if (it + 1 < niter) { issue(it + 1, (it + 1) & 1); cp_wait<1>(); }
        else                { cp_wait<0>(); }
        __syncthreads();

        const float* sA = sm + (it & 1) * STAGE_SZ;
        const float* sB = sA + A_SZ;

#pragma unroll
        for (int s = 0; s < 4; s++) {          // 4 k8-steps per BK=32
            const int k0 = s << 3;
            uint32_t aF[4][4], bF[4][2];
#pragma unroll
            for (int i = 0; i < 4; i++) {
                const float* ap = sA + (wm * 64 + i * 16 + g) * AS_ST + k0 + c;
                aF[i][0] = __float_as_uint(ap[0]);
                aF[i][1] = __float_as_uint(ap[8 * AS_ST]);
                aF[i][2] = __float_as_uint(ap[4]);
                aF[i][3] = __float_as_uint(ap[8 * AS_ST + 4]);
            }
#pragma unroll
            for (int j = 0; j < 4; j++) {
                const float* bp = sB + (k0 + c) * BS_ST + wn * 32 + j * 8 + g;
                bF[j][0] = __float_as_uint(bp[0]);
                bF[j][1] = __float_as_uint(bp[4 * BS_ST]);
            }
#pragma unroll
            for (int i = 0; i < 4; i++)
#pragma unroll
                for (int j = 0; j < 4; j++) {
                    asm volatile(
                        "mma.sync.aligned.m16n8k8.row.col.f32.tf32.tf32.f32 "
                        "{%0,%1,%2,%3}, {%4,%5,%6,%7}, {%8,%9}, {%0,%1,%2,%3};"
                        : "+f"(d[i][j][0]), "+f"(d[i][j][1]),
                          "+f"(d[i][j][2]), "+f"(d[i][j][3])
                        : "r"(aF[i][0]), "r"(aF[i][1]), "r"(aF[i][2]), "r"(aF[i][3]),
                          "r"(bF[j][0]), "r"(bF[j][1]));
                }
        }
        __syncthreads();
    }

    // ---- epilogue: C fragment rows g/g+8, col pairs (2c, 2c+1) -> float2 ----
#pragma unroll
    for (int i = 0; i < 4; i++) {
        const int r0 = by * 128 + wm * 64 + i * 16 + g;
#pragma unroll
        for (int j = 0; j < 4; j++) {
            const int col = bx * 128 + wn * 32 + j * 8 + c * 2;
            *(float2*)(C + (size_t)r0 * N + col)       = make_float2(d[i][j][0], d[i][j][1]);
            *(float2*)(C + (size_t)(r0 + 8) * N + col) = make_float2(d[i][j][2], d[i][j][3]);
        }
    }
}

// Fused QKV projection: grid.x = 24 (16 Q tiles + 4 K + 4 V)
__global__ __launch_bounds__(256, 2)
void qkv_gemm_tf32(const float* __restrict__ x,
                   const float* __restrict__ Wq, const float* __restrict__ Wk,
                   const float* __restrict__ Wv,
                   float* __restrict__ Q, float* __restrict__ K, float* __restrict__ V) {
    const int bx = blockIdx.x;
    const float* B; float* C; int N; int cx;
    if (bx < 16)      { B = Wq; C = Q; N = QDIM;  cx = bx; }
    else if (bx < 20) { B = Wk; C = K; N = KVDIM; cx = bx - 16; }
    else              { B = Wv; C = V; N = KVDIM; cx = bx - 20; }
    gemm_tf32_body(x, B, C, N, HIDn, cx, blockIdx.y);
}

__global__ __launch_bounds__(256, 2)
void gemm_tf32(const float* __restrict__ A, const float* __restrict__ B,
               float* __restrict__ C, int N, int K) {
    gemm_tf32_body(A, B, C, N, K, blockIdx.x, blockIdx.y);
}

// ---------------------------------------------------------------------------
// RoPE (unchanged)
// ---------------------------------------------------------------------------
__global__ void rope_kernel(float* __restrict__ Q, float* __restrict__ K,
                            const float* __restrict__ cs, const float* __restrict__ sn) {
    const int t = blockIdx.x;
    const int h = blockIdx.y;
    const int d = threadIdx.x;        // 0..63
    const int s = t & (Sn - 1);
    const float c1 = cs[s * Dn + d],      s1 = sn[s * Dn + d];
    const float c2 = cs[s * Dn + d + 64], s2 = sn[s * Dn + d + 64];
    float* p = (h < Hn) ? (Q + (size_t)t * QDIM + h * Dn)
                        : (K + (size_t)t * KVDIM + (h - Hn) * Dn);
    const float a = p[d], b = p[d + 64];
    p[d]      = a * c1 - b * s1;
    p[d + 64] = b * c2 + a * s2;
}

// ---------------------------------------------------------------------------
// Causal GQA flash attention, fp32 (unchanged from passing R2 kernel)
// ---------------------------------------------------------------------------
__global__ __launch_bounds__(256)
void flash_kernel(const float* __restrict__ Qg, const float* __restrict__ Kg,
                  const float* __restrict__ Vg, float* __restrict__ Og) {
    extern __shared__ float smf[];
    float* Qs      = smf;                    // [Dn][QS] transposed
    float* KV      = smf + Dn * QS;          // K^T [Dn][QS]  OR  V [BK][Dn]
    float* Ps      = smf + 2 * Dn * QS;      // [BQ][QS]
    float* s_scale = Ps + BQ * QS;           // [BQ]
    float* s_l     = s_scale + BQ;           // [BQ]

    const int tid = threadIdx.x;
    const int h = blockIdx.y;
    const int b = blockIdx.z;
    const int qt = (int)gridDim.x - 1 - (int)blockIdx.x;
    const int qb = qt * BQ;
    const int g = h >> 2;

    const int lr  = tid >> 2;
    const int lc0 = (tid & 3) << 2;

    {
        const float* src = Qg + ((size_t)(b * Sn + qb + lr)) * QDIM + h * Dn;
        const float sc = 0.08838834764831845f;  // 1/sqrt(128)
#pragma unroll
        for (int i = 0; i < 8; i++) {
            const int d0 = lc0 + (i << 4);
            float4 v = *(const float4*)(src + d0);
            Qs[(d0 + 0) * QS + lr] = v.x * sc;
            Qs[(d0 + 1) * QS + lr] = v.y * sc;
            Qs[(d0 + 2) * QS + lr] = v.z * sc;
            Qs[(d0 + 3) * QS + lr] = v.w * sc;
        }
    }

    const int tr  = (tid >> 4) << 2;
    const int tc  = (tid & 15) << 2;
    const int tc8 = (tid & 15) << 3;

    float oreg[4][8];
#pragma unroll
    for (int i = 0; i < 4; i++)
#pragma unroll
        for (int c = 0; c < 8; c++) oreg[i][c] = 0.f;

    float m_r = -1e30f, l_r = 0.f;

    for (int j = 0; j <= qt; j++) {
        {
            const float* src = Kg + ((size_t)(b * Sn + j * BK + lr)) * KVDIM + g * Dn;
#pragma unroll
            for (int i = 0; i < 8; i++) {
                const int d0 = lc0 + (i << 4);
                float4 v = *(const float4*)(src + d0);
                KV[(d0 + 0) * QS + lr] = v.x;
                KV[(d0 + 1) * QS + lr] = v.y;
                KV[(d0 + 2) * QS + lr] = v.z;
                KV[(d0 + 3) * QS + lr] = v.w;
            }
        }
        __syncthreads();

        float acc[4][4];
#pragma unroll
        for (int i = 0; i < 4; i++)
#pragma unroll
            for (int c = 0; c < 4; c++) acc[i][c] = 0.f;
#pragma unroll 4
        for (int kk = 0; kk < Dn; kk++) {
            float4 qv = *(const float4*)(Qs + kk * QS + tr);
            float4 kv = *(const float4*)(KV + kk * QS + tc);
            const float qa[4] = {qv.x, qv.y, qv.z, qv.w};
            const float ka[4] = {kv.x, kv.y, kv.z, kv.w};
#pragma unroll
            for (int i = 0; i < 4; i++)
#pragma unroll
                for (int c = 0; c < 4; c++) acc[i][c] += qa[i] * ka[c];
        }

#pragma unroll
        for (int i = 0; i < 4; i++) {
            const int grow = qb + tr + i;
#pragma unroll
            for (int c = 0; c < 4; c++) {
                const int gcol = j * BK + tc + c;
                Ps[(tr + i) * QS + tc + c] = (gcol > grow) ? -1e30f : acc[i][c];
            }
        }
        __syncthreads();

        {
            const float* src = Vg + ((size_t)(b * Sn + j * BK)) * KVDIM + g * Dn;
#pragma unroll
            for (int i = 0; i < 8; i++) {
                const int idx = (i << 8) + tid;
                const int r = idx >> 5;
                const int d0 = (idx & 31) << 2;
                *(float4*)(KV + r * Dn + d0) = *(const float4*)(src + (size_t)r * KVDIM + d0);
            }
        }

        if (tid < BQ) {
            float* row = Ps + tid * QS;
            float rmax = -1e30f;
#pragma unroll 8
            for (int c = 0; c < BK; c++) rmax = fmaxf(rmax, row[c]);
            const float mnew = fmaxf(m_r, rmax);
            const float corr = __expf(m_r - mnew);
            float rsum = 0.f;
#pragma unroll 8
            for (int c = 0; c < BK; c++) {
                const float p = __expf(row[c] - mnew);
                row[c] = p;
                rsum += p;
            }
            l_r = l_r * corr + rsum;
            m_r = mnew;
            s_scale[tid] = corr;
        }
        __syncthreads();

        float cr[4];
#pragma unroll
        for (int i = 0; i < 4; i++) cr[i] = s_scale[tr + i];
#pragma unroll
        for (int i = 0; i < 4; i++)
#pragma unroll
            for (int c = 0; c < 8; c++) oreg[i][c] *= cr[i];

#pragma unroll 2
        for (int kk = 0; kk < BK; kk++) {
            const float p0 = Ps[(tr + 0) * QS + kk];
            const float p1 = Ps[(tr + 1) * QS + kk];
            const float p2 = Ps[(tr + 2) * QS + kk];
            const float p3 = Ps[(tr + 3) * QS + kk];
            float4 v0 = *(const float4*)(KV + kk * Dn + tc8);
            float4 v1 = *(const float4*)(KV + kk * Dn + tc8 + 4);
            const float va[8] = {v0.x, v0.y, v0.z, v0.w, v1.x, v1.y, v1.z, v1.w};
#pragma unroll
            for (int c = 0; c < 8; c++) {
                oreg[0][c] += p0 * va[c];
                oreg[1][c] += p1 * va[c];
                oreg[2][c] += p2 * va[c];
                oreg[3][c] += p3 * va[c];
            }
        }
        __syncthreads();
    }

    if (tid < BQ) s_l[tid] = l_r;
    __syncthreads();

#pragma unroll
    for (int i = 0; i < 4; i++) {
        const float inv = 1.f / s_l[tr + i];
        float* dst = Og + ((size_t)(b * Sn + qb + tr + i)) * QDIM + h * Dn + tc8;
        *(float4*)(dst)     = make_float4(oreg[i][0] * inv, oreg[i][1] * inv,
                                          oreg[i][2] * inv, oreg[i][3] * inv);
        *(float4*)(dst + 4) = make_float4(oreg[i][4] * inv, oreg[i][5] * inv,
                                          oreg[i][6] * inv, oreg[i][7] * inv);
    }
}

#define FLASH_SMEM ((2 * Dn * QS + BQ * QS + 2 * BQ) * (int)sizeof(float))  // 87552 B

// ---------------------------------------------------------------------------
// Launch: round(x,W*) -> qkv tf32 -> RoPE -> flash(fp32) -> round(O) -> Wo tf32
// Inputs (metadata order): x, cos, sin, Wq, Wk, Wv, Wo.  Output fp32.
// ---------------------------------------------------------------------------
extern "C" void kernel_launch(void* const* d_in, const int* in_sizes, int n_in,
                              void* d_out, int out_size) {
    const float* x  = (const float*)d_in[0];
    const float* cs = (const float*)d_in[1];
    const float* sn = (const float*)d_in[2];
    const float* Wq = (const float*)d_in[3];
    const float* Wk = (const float*)d_in[4];
    const float* Wv = (const float*)d_in[5];
    const float* Wo = (const float*)d_in[6];
    float* out = (float*)d_out;

    float *Qp, *Kp, *Vp, *Op, *Xr, *Wqr, *Wkr, *Wvr, *Wor;
    cudaGetSymbolAddress((void**)&Qp,  g_Q);
    cudaGetSymbolAddress((void**)&Kp,  g_K);
    cudaGetSymbolAddress((void**)&Vp,  g_V);
    cudaGetSymbolAddress((void**)&Op,  g_O);
    cudaGetSymbolAddress((void**)&Xr,  g_Xr);
    cudaGetSymbolAddress((void**)&Wqr, g_Wqr);
    cudaGetSymbolAddress((void**)&Wkr, g_Wkr);
    cudaGetSymbolAddress((void**)&Wvr, g_Wvr);
    cudaGetSymbolAddress((void**)&Wor, g_Wor);

    cudaFuncSetAttribute(flash_kernel,
                         cudaFuncAttributeMaxDynamicSharedMemorySize, FLASH_SMEM);
    cudaFuncSetAttribute(qkv_gemm_tf32,
                         cudaFuncAttributeMaxDynamicSharedMemorySize, GEMM_SMEM);
    cudaFuncSetAttribute(gemm_tf32,
                         cudaFuncAttributeMaxDynamicSharedMemorySize, GEMM_SMEM);

    // tf32-round operands (rna rounding: zero-mean error, no truncation bias)
    const int TPB = 256;
    round_tf32_kernel<<<(NTOK * HIDn / 4 + TPB - 1) / TPB, TPB>>>(x,  Xr,  NTOK * HIDn / 4);
    round_tf32_kernel<<<(HIDn * QDIM / 4 + TPB - 1) / TPB, TPB>>>(Wq, Wqr, HIDn * QDIM / 4);
    round_tf32_kernel<<<(HIDn * KVDIM / 4 + TPB - 1) / TPB, TPB>>>(Wk, Wkr, HIDn * KVDIM / 4);
    round_tf32_kernel<<<(HIDn * KVDIM / 4 + TPB - 1) / TPB, TPB>>>(Wv, Wvr, HIDn * KVDIM / 4);
    round_tf32_kernel<<<(QDIM * HIDn / 4 + TPB - 1) / TPB, TPB>>>(Wo, Wor, QDIM * HIDn / 4);

    // Fused QKV projections (tensor cores)
    qkv_gemm_tf32<<<dim3(24, NTOK / 128), 256, GEMM_SMEM>>>(Xr, Wqr, Wkr, Wvr, Qp, Kp, Vp);

    // RoPE on Q and K
    rope_kernel<<<dim3(NTOK, Hn + Gn), 64>>>(Qp, Kp, cs, sn);

    // Causal GQA flash attention (fp32)
    flash_kernel<<<dim3(Sn / BQ, Hn, Bn), 256, FLASH_SMEM>>>(Qp, Kp, Vp, Op);

    // Round O in place, then output projection (tensor cores)
    round_tf32_kernel<<<(NTOK * QDIM / 4 + TPB - 1) / TPB, TPB>>>(Op, Op, NTOK * QDIM / 4);
    gemm_tf32<<<dim3(HIDn / 128, NTOK / 128), 256, GEMM_SMEM>>>(Op, Wor, out, HIDn, QDIM);
}

// round 4
// speedup vs baseline: 2.1284x; 1.1821x over previous
#include <cuda_runtime.h>
#include <math.h>
#include <stdint.h>

// Problem constants
#define Bn   2
#define Sn   2048
#define HIDn 2048
#define Hn   16
#define Gn   4
#define Dn   128
#define NTOK (Bn * Sn)      // 4096
#define QDIM (Hn * Dn)      // 2048
#define KVDIM (Gn * Dn)     // 512

// Flash tiling
#define BQ 64
#define BK 64

// ---------------------------------------------------------------------------
// Scratch (__device__ globals per allocation-free rule)
// ---------------------------------------------------------------------------
__device__ float g_Q[NTOK * QDIM];
__device__ float g_K[NTOK * KVDIM];
__device__ float g_V[NTOK * KVDIM];
__device__ float g_O[NTOK * QDIM];
__device__ float g_Xr[NTOK * HIDn];
__device__ float g_Wqr[HIDn * QDIM];
__device__ float g_Wkr[HIDn * KVDIM];
__device__ float g_Wvr[HIDn * KVDIM];
__device__ float g_Wor[QDIM * HIDn];

// ---------------------------------------------------------------------------
// tf32 round-to-nearest + rounding pass
// ---------------------------------------------------------------------------
__device__ __forceinline__ float tf32r(float x) {
    uint32_t u;
    asm("cvt.rna.tf32.f32 %0, %1;" : "=r"(u) : "f"(x));
    return __uint_as_float(u);
}

__global__ void round_tf32_kernel(const float* __restrict__ in,
                                  float* __restrict__ out, int n4) {
    int i = blockIdx.x * blockDim.x + threadIdx.x;
    if (i < n4) {
        float4 v = ((const float4*)in)[i];
        v.x = tf32r(v.x); v.y = tf32r(v.y); v.z = tf32r(v.z); v.w = tf32r(v.w);
        ((float4*)out)[i] = v;
    }
}

// ---------------------------------------------------------------------------
// cp.async helpers
// ---------------------------------------------------------------------------
__device__ __forceinline__ void cp_async16(uint32_t dst, const void* src) {
    asm volatile("cp.async.cg.shared.global [%0], [%1], 16;" :: "r"(dst), "l"(src));
}
__device__ __forceinline__ void cp_commit() {
    asm volatile("cp.async.commit_group;");
}
template <int N>
__device__ __forceinline__ void cp_wait() {
    asm volatile("cp.async.wait_group %0;" :: "n"(N));
}

// ---------------------------------------------------------------------------
// mma.m16n8k8 tf32 helper
// ---------------------------------------------------------------------------
__device__ __forceinline__
void mma_tf32(float* d, uint32_t a0, uint32_t a1, uint32_t a2, uint32_t a3,
              uint32_t b0, uint32_t b1) {
    asm volatile(
        "mma.sync.aligned.m16n8k8.row.col.f32.tf32.tf32.f32 "
        "{%0,%1,%2,%3}, {%4,%5,%6,%7}, {%8,%9}, {%0,%1,%2,%3};"
        : "+f"(d[0]), "+f"(d[1]), "+f"(d[2]), "+f"(d[3])
        : "r"(a0), "r"(a1), "r"(a2), "r"(a3), "r"(b0), "r"(b1));
}

// ---------------------------------------------------------------------------
// tf32 tensor-core GEMM (unchanged from R3, passing): C = A @ B
// ---------------------------------------------------------------------------
#define AS_ST 36
#define BS_ST 136
#define A_SZ (128 * AS_ST)
#define B_SZ (32 * BS_ST)
#define STAGE_SZ (A_SZ + B_SZ)
#define GEMM_SMEM (2 * STAGE_SZ * (int)sizeof(float))   // 71680 B

__device__ __forceinline__
void gemm_tf32_body(const float* __restrict__ A, const float* __restrict__ B,
                    float* __restrict__ C, int N, int K, int bx, int by) {
    extern __shared__ float sm[];
    const int tid  = threadIdx.x;
    const int w    = tid >> 5, lane = tid & 31;
    const int wm   = w >> 2,   wn   = w & 3;
    const int g    = lane >> 2, c   = lane & 3;

    const uint32_t smbase = (uint32_t)__cvta_generic_to_shared(sm);

    float d[4][4][4];
#pragma unroll
    for (int i = 0; i < 4; i++)
#pragma unroll
        for (int j = 0; j < 4; j++)
#pragma unroll
            for (int r = 0; r < 4; r++) d[i][j][r] = 0.f;

    const int niter = K / 32;

    auto issue = [&](int it, int s) {
        const uint32_t sAu = smbase + (uint32_t)(s * STAGE_SZ) * 4u;
        const uint32_t sBu = sAu + (uint32_t)A_SZ * 4u;
        const float* Ag = A + (size_t)(by * 128) * K + it * 32;
        const float* Bg = B + (size_t)(it * 32) * N + bx * 128;
#pragma unroll
        for (int i = 0; i < 4; i++) {
            const int f = i * 256 + tid;
            const int m  = f >> 3, kc = (f & 7) << 2;
            cp_async16(sAu + (uint32_t)(m * AS_ST + kc) * 4u,
                       Ag + (size_t)m * K + kc);
            const int kb = f >> 5, nc = (f & 31) << 2;
            cp_async16(sBu + (uint32_t)(kb * BS_ST + nc) * 4u,
                       Bg + (size_t)kb * N + nc);
        }
        cp_commit();
    };

    issue(0, 0);

    for (int it = 0; it < niter; it++) {
        if (it + 1 < niter) { issue(it + 1, (it + 1) & 1); cp_wait<1>(); }
        else                { cp_wait<0>(); }
        __syncthreads();

        const float* sA = sm + (it & 1) * STAGE_SZ;
        const float* sB = sA + A_SZ;

#pragma unroll
        for (int s = 0; s < 4; s++) {
            const int k0 = s << 3;
            uint32_t aF[4][4], bF[4][2];
#pragma unroll
            for (int i = 0; i < 4; i++) {
                const float* ap = sA + (wm * 64 + i * 16 + g) * AS_ST + k0 + c;
                aF[i][0] = __float_as_uint(ap[0]);
                aF[i][1] = __float_as_uint(ap[8 * AS_ST]);
                aF[i][2] = __float_as_uint(ap[4]);
                aF[i][3] = __float_as_uint(ap[8 * AS_ST + 4]);
            }
#pragma unroll
            for (int j = 0; j < 4; j++) {
                const float* bp = sB + (k0 + c) * BS_ST + wn * 32 + j * 8 + g;
                bF[j][0] = __float_as_uint(bp[0]);
                bF[j][1] = __float_as_uint(bp[4 * BS_ST]);
            }
#pragma unroll
            for (int i = 0; i < 4; i++)
#pragma unroll
                for (int j = 0; j < 4; j++)
                    mma_tf32(d[i][j], aF[i][0], aF[i][1], aF[i][2], aF[i][3],
                             bF[j][0], bF[j][1]);
        }
        __syncthreads();
    }

#pragma unroll
    for (int i = 0; i < 4; i++) {
        const int r0 = by * 128 + wm * 64 + i * 16 + g;
#pragma unroll
        for (int j = 0; j < 4; j++) {
            const int col = bx * 128 + wn * 32 + j * 8 + c * 2;
            *(float2*)(C + (size_t)r0 * N + col)       = make_float2(d[i][j][0], d[i][j][1]);
            *(float2*)(C + (size_t)(r0 + 8) * N + col) = make_float2(d[i][j][2], d[i][j][3]);
        }
    }
}

__global__ __launch_bounds__(256, 2)
void qkv_gemm_tf32(const float* __restrict__ x,
                   const float* __restrict__ Wq, const float* __restrict__ Wk,
                   const float* __restrict__ Wv,
                   float* __restrict__ Q, float* __restrict__ K, float* __restrict__ V) {
    const int bx = blockIdx.x;
    const float* B; float* C; int N; int cx;
    if (bx < 16)      { B = Wq; C = Q; N = QDIM;  cx = bx; }
    else if (bx < 20) { B = Wk; C = K; N = KVDIM; cx = bx - 16; }
    else              { B = Wv; C = V; N = KVDIM; cx = bx - 20; }
    gemm_tf32_body(x, B, C, N, HIDn, cx, blockIdx.y);
}

__global__ __launch_bounds__(256, 2)
void gemm_tf32(const float* __restrict__ A, const float* __restrict__ B,
               float* __restrict__ C, int N, int K) {
    gemm_tf32_body(A, B, C, N, K, blockIdx.x, blockIdx.y);
}

// ---------------------------------------------------------------------------
// RoPE + tf32 pre-rounding. Q additionally pre-scaled by 1/sqrt(D).
// grid: (NTOK, Hn + Gn + Gn): [0,Hn) Q-rope, [Hn,Hn+Gn) K-rope, rest V-round.
// ---------------------------------------------------------------------------
__global__ void rope_round_kernel(float* __restrict__ Q, float* __restrict__ K,
                                  float* __restrict__ V,
                                  const float* __restrict__ cs,
                                  const float* __restrict__ sn) {
    const int t = blockIdx.x;
    const int h = blockIdx.y;
    const int d = threadIdx.x;        // 0..63
    const int s = t & (Sn - 1);

    if (h >= Hn + Gn) {               // V: round only
        float* p = V + (size_t)t * KVDIM + (h - Hn - Gn) * Dn;
        p[d]      = tf32r(p[d]);
        p[d + 64] = tf32r(p[d + 64]);
        return;
    }
    const float c1 = cs[s * Dn + d],      s1 = sn[s * Dn + d];
    const float c2 = cs[s * Dn + d + 64], s2 = sn[s * Dn + d + 64];
    const bool isQ = (h < Hn);
    float* p = isQ ? (Q + (size_t)t * QDIM + h * Dn)
                   : (K + (size_t)t * KVDIM + (h - Hn) * Dn);
    const float sc = isQ ? 0.08838834764831845f : 1.0f;   // 1/sqrt(128)
    const float a = p[d], b = p[d + 64];
    p[d]      = tf32r((a * c1 - b * s1) * sc);
    p[d + 64] = tf32r((b * c2 + a * s2) * sc);
}

// ---------------------------------------------------------------------------
// Causal GQA flash attention on tf32 tensor cores.
// BQ=64 q-rows, BK=64 k-cols, D=128. 256 threads (8 warps).
// Q/K/V streamed by cp.async (K/V double-buffered, prefetch overlaps compute).
// Natural row-major smem layouts; strides chosen conflict-free for fragments:
//   Q,K stride 132 (bank 4g+c), V stride 136 (8c+g), P stride 68 (4g+c).
// S staged to smem fp32 -> per-row online softmax (tid<64) -> P (tf32-rna)
// -> PV mma with O accumulators in registers.
// ---------------------------------------------------------------------------
#define QST 132
#define KST 132
#define VST 136
#define PST 68
#define Q_SZ  (BQ * QST)              // 8448 floats
#define K_SZ  (BK * KST)              // 8448
#define V_SZ  (BK * VST)              // 8704
#define P_OFF (Q_SZ + 2 * K_SZ + 2 * V_SZ)
#define FLASH_SMEM ((P_OFF + BQ * PST + 2 * BQ) * (int)sizeof(float))  // 188992 B

__global__ __launch_bounds__(256)
void flash_tc_kernel(const float* __restrict__ Qg, const float* __restrict__ Kg,
                     const float* __restrict__ Vg, float* __restrict__ Og) {
    extern __shared__ float smf[];
    float* Qs = smf;                          // [BQ][132]
    float* Ks = smf + Q_SZ;                   // 2 x [BK][132]
    float* Vs = smf + Q_SZ + 2 * K_SZ;        // 2 x [BK][136]
    float* Ps = smf + P_OFF;                  // [BQ][68]
    float* s_scale = Ps + BQ * PST;           // [BQ]
    float* s_l     = s_scale + BQ;            // [BQ]
    const uint32_t smbase = (uint32_t)__cvta_generic_to_shared(smf);

    const int tid = threadIdx.x;
    const int w = tid >> 5, lane = tid & 31;
    const int g = lane >> 2, c = lane & 3;
    const int wm = w & 3;                     // row tile: wm*16
    const int wn = w >> 2;                    // 0..1

    const int h = blockIdx.y;
    const int b = blockIdx.z;
    const int qt = (int)gridDim.x - 1 - (int)blockIdx.x;  // longest first
    const int qb = qt * BQ;
    const int gh = h >> 2;                    // GQA group

    // ---- cp.async loaders ----
    auto issueQ = [&]() {
        const float* src = Qg + ((size_t)(b * Sn + qb)) * QDIM + h * Dn;
#pragma unroll
        for (int i = 0; i < 8; i++) {
            const int f = i * 256 + tid;
            const int r = f >> 5, c4 = (f & 31) << 2;
            cp_async16(smbase + (uint32_t)(r * QST + c4) * 4u,
                       src + (size_t)r * QDIM + c4);
        }
    };
    auto issueKV = [&](int j, int s) {
        const float* ksrc = Kg + ((size_t)(b * Sn + j * BK)) * KVDIM + gh * Dn;
        const float* vsrc = Vg + ((size_t)(b * Sn + j * BK)) * KVDIM + gh * Dn;
        const uint32_t kb = smbase + (uint32_t)(Q_SZ + s * K_SZ) * 4u;
        const uint32_t vb = smbase + (uint32_t)(Q_SZ + 2 * K_SZ + s * V_SZ) * 4u;
#pragma unroll
        for (int i = 0; i < 8; i++) {
            const int f = i * 256 + tid;
            const int r = f >> 5, c4 = (f & 31) << 2;
            cp_async16(kb + (uint32_t)(r * KST + c4) * 4u, ksrc + (size_t)r * KVDIM + c4);
            cp_async16(vb + (uint32_t)(r * VST + c4) * 4u, vsrc + (size_t)r * KVDIM + c4);
        }
        cp_commit();
    };

    issueQ();
    issueKV(0, 0);                     // group 0 (includes Q)
    if (qt >= 1) issueKV(1, 1);        // group 1

    float oreg[8][4];
#pragma unroll
    for (int n = 0; n < 8; n++)
#pragma unroll
        for (int r = 0; r < 4; r++) oreg[n][r] = 0.f;

    float m_r = -1e30f, l_r = 0.f;     // row state, owned by tid<64

    for (int j = 0; j <= qt; j++) {
        if (j < qt) cp_wait<1>(); else cp_wait<0>();
        __syncthreads();               // stage j&1 ready

        const float* Kj = Ks + (j & 1) * K_SZ;
        const float* Vj = Vs + (j & 1) * V_SZ;

        // ---- S = Q K^T : warp tile 16x32 ----
        float sacc[4][4];
#pragma unroll
        for (int n = 0; n < 4; n++)
#pragma unroll
            for (int r = 0; r < 4; r++) sacc[n][r] = 0.f;

#pragma unroll
        for (int ks = 0; ks < 16; ks++) {
            const int k0 = ks << 3;
            const float* ap = Qs + (wm * 16 + g) * QST + k0 + c;
            const uint32_t a0 = __float_as_uint(ap[0]);
            const uint32_t a1 = __float_as_uint(ap[8 * QST]);
            const uint32_t a2 = __float_as_uint(ap[4]);
            const uint32_t a3 = __float_as_uint(ap[8 * QST + 4]);
#pragma unroll
            for (int nt = 0; nt < 4; nt++) {
                const float* bp = Kj + (wn * 32 + nt * 8 + g) * KST + k0 + c;
                mma_tf32(sacc[nt], a0, a1, a2, a3,
                         __float_as_uint(bp[0]), __float_as_uint(bp[4]));
            }
        }

        // ---- stage S -> Ps ----
#pragma unroll
        for (int nt = 0; nt < 4; nt++) {
            const int row = wm * 16 + g;
            const int col = wn * 32 + nt * 8 + 2 * c;
            *(float2*)(Ps + row * PST + col)       = make_float2(sacc[nt][0], sacc[nt][1]);
            *(float2*)(Ps + (row + 8) * PST + col) = make_float2(sacc[nt][2], sacc[nt][3]);
        }
        __syncthreads();

        // ---- online softmax (one thread per row) ----
        if (tid < BQ) {
            float* row = Ps + tid * PST;
            const int grow = qb + tid;
            const int nvalid = (j == qt) ? (grow - j * BK + 1) : BK;
            float rmax = -1e30f;
#pragma unroll 8
            for (int cc = 0; cc < BK; cc++)
                if (cc < nvalid) rmax = fmaxf(rmax, row[cc]);
            const float mnew = fmaxf(m_r, rmax);
            const float corr = __expf(m_r - mnew);
            float rsum = 0.f;
#pragma unroll 8
            for (int cc = 0; cc < BK; cc++) {
                const float p = (cc < nvalid) ? tf32r(__expf(row[cc] - mnew)) : 0.f;
                row[cc] = p;
                rsum += p;
            }
            l_r = l_r * corr + rsum;
            m_r = mnew;
            s_scale[tid] = corr;
        }
        __syncthreads();

        // ---- O rescale + O += P @ V : warp tile 16 x 64 ----
        const float cr0 = s_scale[wm * 16 + g];
        const float cr1 = s_scale[wm * 16 + g + 8];
#pragma unroll
        for (int n = 0; n < 8; n++) {
            oreg[n][0] *= cr0; oreg[n][1] *= cr0;
            oreg[n][2] *= cr1; oreg[n][3] *= cr1;
        }
#pragma unroll
        for (int ks = 0; ks < 8; ks++) {
            const int k0 = ks << 3;
            const float* ap = Ps + (wm * 16 + g) * PST + k0 + c;
            const uint32_t a0 = __float_as_uint(ap[0]);
            const uint32_t a1 = __float_as_uint(ap[8 * PST]);
            const uint32_t a2 = __float_as_uint(ap[4]);
            const uint32_t a3 = __float_as_uint(ap[8 * PST + 4]);
#pragma unroll
            for (int nt = 0; nt < 8; nt++) {
                const float* bp = Vj + (k0 + c) * VST + wn * 64 + nt * 8 + g;
                mma_tf32(oreg[nt], a0, a1, a2, a3,
                         __float_as_uint(bp[0]), __float_as_uint(bp[4 * VST]));
            }
        }
        __syncthreads();               // done reading stage j&1 + Ps

        if (j + 2 <= qt) issueKV(j + 2, j & 1);
    }

    if (tid < BQ) s_l[tid] = l_r;
    __syncthreads();

    const float inv0 = 1.f / s_l[wm * 16 + g];
    const float inv1 = 1.f / s_l[wm * 16 + g + 8];
    const int row0 = b * Sn + qb + wm * 16 + g;
#pragma unroll
    for (int nt = 0; nt < 8; nt++) {
        const int col = h * Dn + wn * 64 + nt * 8 + 2 * c;
        *(float2*)(Og + (size_t)row0 * QDIM + col) =
            make_float2(oreg[nt][0] * inv0, oreg[nt][1] * inv0);
        *(float2*)(Og + (size_t)(row0 + 8) * QDIM + col) =
            make_float2(oreg[nt][2] * inv1, oreg[nt][3] * inv1);
    }
}

// ---------------------------------------------------------------------------
// Launch pipeline
// ---------------------------------------------------------------------------
extern "C" void kernel_launch(void* const* d_in, const int* in_sizes, int n_in,
                              void* d_out, int out_size) {
    const float* x  = (const float*)d_in[0];
    const float* cs = (const float*)d_in[1];
    const float* sn = (const float*)d_in[2];
    const float* Wq = (const float*)d_in[3];
    const float* Wk = (const float*)d_in[4];
    const float* Wv = (const float*)d_in[5];
    const float* Wo = (const float*)d_in[6];
    float* out = (float*)d_out;

    float *Qp, *Kp, *Vp, *Op, *Xr, *Wqr, *Wkr, *Wvr, *Wor;
    cudaGetSymbolAddress((void**)&Qp,  g_Q);
    cudaGetSymbolAddress((void**)&Kp,  g_K);
    cudaGetSymbolAddress((void**)&Vp,  g_V);
    cudaGetSymbolAddress((void**)&Op,  g_O);
    cudaGetSymbolAddress((void**)&Xr,  g_Xr);
    cudaGetSymbolAddress((void**)&Wqr, g_Wqr);
    cudaGetSymbolAddress((void**)&Wkr, g_Wkr);
    cudaGetSymbolAddress((void**)&Wvr, g_Wvr);
    cudaGetSymbolAddress((void**)&Wor, g_Wor);

    cudaFuncSetAttribute(flash_tc_kernel,
                         cudaFuncAttributeMaxDynamicSharedMemorySize, FLASH_SMEM);
    cudaFuncSetAttribute(qkv_gemm_tf32,
                         cudaFuncAttributeMaxDynamicSharedMemorySize, GEMM_SMEM);
    cudaFuncSetAttribute(gemm_tf32,
                         cudaFuncAttributeMaxDynamicSharedMemorySize, GEMM_SMEM);

    const int TPB = 256;
    round_tf32_kernel<<<(NTOK * HIDn / 4 + TPB - 1) / TPB, TPB>>>(x,  Xr,  NTOK * HIDn / 4);
    round_tf32_kernel<<<(HIDn * QDIM / 4 + TPB - 1) / TPB, TPB>>>(Wq, Wqr, HIDn * QDIM / 4);
    round_tf32_kernel<<<(HIDn * KVDIM / 4 + TPB - 1) / TPB, TPB>>>(Wk, Wkr, HIDn * KVDIM / 4);
    round_tf32_kernel<<<(HIDn * KVDIM / 4 + TPB - 1) / TPB, TPB>>>(Wv, Wvr, HIDn * KVDIM / 4);
    round_tf32_kernel<<<(QDIM * HIDn / 4 + TPB - 1) / TPB, TPB>>>(Wo, Wor, QDIM * HIDn / 4);

    // QKV projections (tf32 tensor cores)
    qkv_gemm_tf32<<<dim3(24, NTOK / 128), 256, GEMM_SMEM>>>(Xr, Wqr, Wkr, Wvr, Qp, Kp, Vp);

    // RoPE + 1/sqrt(D) fold + tf32 rounding of Q,K,V
    rope_round_kernel<<<dim3(NTOK, Hn + Gn + Gn), 64>>>(Qp, Kp, Vp, cs, sn);

    // Flash attention on tensor cores
    flash_tc_kernel<<<dim3(Sn / BQ, Hn, Bn), 256, FLASH_SMEM>>>(Qp, Kp, Vp, Op);

    // Round O, then output projection
    round_tf32_kernel<<<(NTOK * QDIM / 4 + TPB - 1) / TPB, TPB>>>(Op, Op, NTOK * QDIM / 4);
    gemm_tf32<<<dim3(HIDn / 128, NTOK / 128), 256, GEMM_SMEM>>>(Op, Wor, out, HIDn, QDIM);
}

// round 5
// speedup vs baseline: 3.5222x; 1.6548x over previous
#include <cuda_runtime.h>
#include <math.h>
#include <stdint.h>

// Problem constants
#define Bn   2
#define Sn   2048
#define HIDn 2048
#define Hn   16
#define Gn   4
#define Dn   128
#define NTOK (Bn * Sn)      // 4096
#define QDIM (Hn * Dn)      // 2048
#define KVDIM (Gn * Dn)     // 512

// Flash tiling
#define BQ 64
#define BK 64

// ---------------------------------------------------------------------------
// Scratch (__device__ globals per allocation-free rule)
// ---------------------------------------------------------------------------
__device__ float g_Q[NTOK * QDIM];
__device__ float g_K[NTOK * KVDIM];
__device__ float g_V[NTOK * KVDIM];
__device__ float g_O[NTOK * QDIM];
__device__ float g_Xr[NTOK * HIDn];
__device__ float g_Wqr[HIDn * QDIM];
__device__ float g_Wkr[HIDn * KVDIM];
__device__ float g_Wvr[HIDn * KVDIM];
__device__ float g_Wor[QDIM * HIDn];

// ---------------------------------------------------------------------------
// tf32 round-to-nearest + rounding pass
// ---------------------------------------------------------------------------
__device__ __forceinline__ float tf32r(float x) {
    uint32_t u;
    asm("cvt.rna.tf32.f32 %0, %1;" : "=r"(u) : "f"(x));
    return __uint_as_float(u);
}

__global__ void round_tf32_kernel(const float* __restrict__ in,
                                  float* __restrict__ out, int n4) {
    int i = blockIdx.x * blockDim.x + threadIdx.x;
    if (i < n4) {
        float4 v = ((const float4*)in)[i];
        v.x = tf32r(v.x); v.y = tf32r(v.y); v.z = tf32r(v.z); v.w = tf32r(v.w);
        ((float4*)out)[i] = v;
    }
}

// ---------------------------------------------------------------------------
// cp.async helpers
// ---------------------------------------------------------------------------
__device__ __forceinline__ void cp_async16(uint32_t dst, const void* src) {
    asm volatile("cp.async.cg.shared.global [%0], [%1], 16;" :: "r"(dst), "l"(src));
}
__device__ __forceinline__ void cp_commit() {
    asm volatile("cp.async.commit_group;");
}
template <int N>
__device__ __forceinline__ void cp_wait() {
    asm volatile("cp.async.wait_group %0;" :: "n"(N));
}

// ---------------------------------------------------------------------------
// mma.m16n8k8 tf32 helper
// ---------------------------------------------------------------------------
__device__ __forceinline__
void mma_tf32(float* d, uint32_t a0, uint32_t a1, uint32_t a2, uint32_t a3,
              uint32_t b0, uint32_t b1) {
    asm volatile(
        "mma.sync.aligned.m16n8k8.row.col.f32.tf32.tf32.f32 "
        "{%0,%1,%2,%3}, {%4,%5,%6,%7}, {%8,%9}, {%0,%1,%2,%3};"
        : "+f"(d[0]), "+f"(d[1]), "+f"(d[2]), "+f"(d[3])
        : "r"(a0), "r"(a1), "r"(a2), "r"(a3), "r"(b0), "r"(b1));
}

// ---------------------------------------------------------------------------
// tf32 tensor-core GEMM (unchanged, passing): C = A @ B
// ---------------------------------------------------------------------------
#define AS_ST 36
#define BS_ST 136
#define A_SZ (128 * AS_ST)
#define B_SZ (32 * BS_ST)
#define STAGE_SZ (A_SZ + B_SZ)
#define GEMM_SMEM (2 * STAGE_SZ * (int)sizeof(float))   // 71680 B

__device__ __forceinline__
void gemm_tf32_body(const float* __restrict__ A, const float* __restrict__ B,
                    float* __restrict__ C, int N, int K, int bx, int by) {
    extern __shared__ float sm[];
    const int tid  = threadIdx.x;
    const int w    = tid >> 5, lane = tid & 31;
    const int wm   = w >> 2,   wn   = w & 3;
    const int g    = lane >> 2, c   = lane & 3;

    const uint32_t smbase = (uint32_t)__cvta_generic_to_shared(sm);

    float d[4][4][4];
#pragma unroll
    for (int i = 0; i < 4; i++)
#pragma unroll
        for (int j = 0; j < 4; j++)
#pragma unroll
            for (int r = 0; r < 4; r++) d[i][j][r] = 0.f;

    const int niter = K / 32;

    auto issue = [&](int it, int s) {
        const uint32_t sAu = smbase + (uint32_t)(s * STAGE_SZ) * 4u;
        const uint32_t sBu = sAu + (uint32_t)A_SZ * 4u;
        const float* Ag = A + (size_t)(by * 128) * K + it * 32;
        const float* Bg = B + (size_t)(it * 32) * N + bx * 128;
#pragma unroll
        for (int i = 0; i < 4; i++) {
            const int f = i * 256 + tid;
            const int m  = f >> 3, kc = (f & 7) << 2;
            cp_async16(sAu + (uint32_t)(m * AS_ST + kc) * 4u,
                       Ag + (size_t)m * K + kc);
            const int kb = f >> 5, nc = (f & 31) << 2;
            cp_async16(sBu + (uint32_t)(kb * BS_ST + nc) * 4u,
                       Bg + (size_t)kb * N + nc);
        }
        cp_commit();
    };

    issue(0, 0);

    for (int it = 0; it < niter; it++) {
        if (it + 1 < niter) { issue(it + 1, (it + 1) & 1); cp_wait<1>(); }
        else                { cp_wait<0>(); }
        __syncthreads();

        const float* sA = sm + (it & 1) * STAGE_SZ;
        const float* sB = sA + A_SZ;

#pragma unroll
        for (int s = 0; s < 4; s++) {
            const int k0 = s << 3;
            uint32_t aF[4][4], bF[4][2];
#pragma unroll
            for (int i = 0; i < 4; i++) {
                const float* ap = sA + (wm * 64 + i * 16 + g) * AS_ST + k0 + c;
                aF[i][0] = __float_as_uint(ap[0]);
                aF[i][1] = __float_as_uint(ap[8 * AS_ST]);
                aF[i][2] = __float_as_uint(ap[4]);
                aF[i][3] = __float_as_uint(ap[8 * AS_ST + 4]);
            }
#pragma unroll
            for (int j = 0; j < 4; j++) {
                const float* bp = sB + (k0 + c) * BS_ST + wn * 32 + j * 8 + g;
                bF[j][0] = __float_as_uint(bp[0]);
                bF[j][1] = __float_as_uint(bp[4 * BS_ST]);
            }
#pragma unroll
            for (int i = 0; i < 4; i++)
#pragma unroll
                for (int j = 0; j < 4; j++)
                    mma_tf32(d[i][j], aF[i][0], aF[i][1], aF[i][2], aF[i][3],
                             bF[j][0], bF[j][1]);
        }
        __syncthreads();
    }

#pragma unroll
    for (int i = 0; i < 4; i++) {
        const int r0 = by * 128 + wm * 64 + i * 16 + g;
#pragma unroll
        for (int j = 0; j < 4; j++) {
            const int col = bx * 128 + wn * 32 + j * 8 + c * 2;
            *(float2*)(C + (size_t)r0 * N + col)       = make_float2(d[i][j][0], d[i][j][1]);
            *(float2*)(C + (size_t)(r0 + 8) * N + col) = make_float2(d[i][j][2], d[i][j][3]);
        }
    }
}

__global__ __launch_bounds__(256, 2)
void qkv_gemm_tf32(const float* __restrict__ x,
                   const float* __restrict__ Wq, const float* __restrict__ Wk,
                   const float* __restrict__ Wv,
                   float* __restrict__ Q, float* __restrict__ K, float* __restrict__ V) {
    const int bx = blockIdx.x;
    const float* B; float* C; int N; int cx;
    if (bx < 16)      { B = Wq; C = Q; N = QDIM;  cx = bx; }
    else if (bx < 20) { B = Wk; C = K; N = KVDIM; cx = bx - 16; }
    else              { B = Wv; C = V; N = KVDIM; cx = bx - 20; }
    gemm_tf32_body(x, B, C, N, HIDn, cx, blockIdx.y);
}

__global__ __launch_bounds__(256, 2)
void gemm_tf32(const float* __restrict__ A, const float* __restrict__ B,
               float* __restrict__ C, int N, int K) {
    gemm_tf32_body(A, B, C, N, K, blockIdx.x, blockIdx.y);
}

// ---------------------------------------------------------------------------
// RoPE + tf32 pre-rounding. Q additionally pre-scaled by 1/sqrt(D).
// ---------------------------------------------------------------------------
__global__ void rope_round_kernel(float* __restrict__ Q, float* __restrict__ K,
                                  float* __restrict__ V,
                                  const float* __restrict__ cs,
                                  const float* __restrict__ sn) {
    const int t = blockIdx.x;
    const int h = blockIdx.y;
    const int d = threadIdx.x;        // 0..63
    const int s = t & (Sn - 1);

    if (h >= Hn + Gn) {               // V: round only
        float* p = V + (size_t)t * KVDIM + (h - Hn - Gn) * Dn;
        p[d]      = tf32r(p[d]);
        p[d + 64] = tf32r(p[d + 64]);
        return;
    }
    const float c1 = cs[s * Dn + d],      s1 = sn[s * Dn + d];
    const float c2 = cs[s * Dn + d + 64], s2 = sn[s * Dn + d + 64];
    const bool isQ = (h < Hn);
    float* p = isQ ? (Q + (size_t)t * QDIM + h * Dn)
                   : (K + (size_t)t * KVDIM + (h - Hn) * Dn);
    const float sc = isQ ? 0.08838834764831845f : 1.0f;   // 1/sqrt(128)
    const float a = p[d], b = p[d + 64];
    p[d]      = tf32r((a * c1 - b * s1) * sc);
    p[d + 64] = tf32r((b * c2 + a * s2) * sc);
}

// ---------------------------------------------------------------------------
// Causal GQA flash attention, tf32 tensor cores, PARALLEL register softmax.
// BQ=64, BK=64, D=128, 256 threads (8 warps: wm=w&3 row-tile, wn=w>>2 col-half).
// Q fragments hoisted to registers (read once); Ps aliases the dead Qs buffer.
// Row max/sum: shfl.bfly intra-warp + 2-partial smem combine cross-warp;
// m/l state in registers, replicated per thread.
// ---------------------------------------------------------------------------
#define QST 132
#define KST 132
#define VST 136
#define PST 68
#define Q_SZ  (BQ * QST)              // 8448 floats
#define K_SZ  (BK * KST)              // 8448
#define V_SZ  (BK * VST)              // 8704
#define PART_OFF (Q_SZ + 2 * K_SZ + 2 * V_SZ)
#define FLASH_SMEM ((PART_OFF + 256) * (int)sizeof(float))  // 172,032 B

__global__ __launch_bounds__(256)
void flash_tc_kernel(const float* __restrict__ Qg, const float* __restrict__ Kg,
                     const float* __restrict__ Vg, float* __restrict__ Og) {
    extern __shared__ float smf[];
    float* Qs = smf;                          // [BQ][132] (dead after frag hoist)
    float* Ps = smf;                          // [BQ][68]  aliases Qs
    float* Ks = smf + Q_SZ;                   // 2 x [BK][132]
    float* Vs = smf + Q_SZ + 2 * K_SZ;        // 2 x [BK][136]
    float* s_part = smf + PART_OFF;           // [2][64] row-max partials
    float* s_psum = s_part + 128;             // [2][64] row-sum partials
    const uint32_t smbase = (uint32_t)__cvta_generic_to_shared(smf);

    const int tid = threadIdx.x;
    const int w = tid >> 5, lane = tid & 31;
    const int g = lane >> 2, c = lane & 3;
    const int wm = w & 3;                     // row tile: wm*16
    const int wn = w >> 2;                    // col half: 0..1

    const int h = blockIdx.y;
    const int b = blockIdx.z;
    const int qt = (int)gridDim.x - 1 - (int)blockIdx.x;  // longest first
    const int qb = qt * BQ;
    const int gh = h >> 2;                    // GQA group

    const int rr0 = wm * 16 + g;              // this thread's two rows
    const int rr1 = rr0 + 8;

    // ---- cp.async loaders ----
    auto issueQ = [&]() {
        const float* src = Qg + ((size_t)(b * Sn + qb)) * QDIM + h * Dn;
#pragma unroll
        for (int i = 0; i < 8; i++) {
            const int f = i * 256 + tid;
            const int r = f >> 5, c4 = (f & 31) << 2;
            cp_async16(smbase + (uint32_t)(r * QST + c4) * 4u,
                       src + (size_t)r * QDIM + c4);
        }
    };
    auto issueKV = [&](int j, int s) {
        const float* ksrc = Kg + ((size_t)(b * Sn + j * BK)) * KVDIM + gh * Dn;
        const float* vsrc = Vg + ((size_t)(b * Sn + j * BK)) * KVDIM + gh * Dn;
        const uint32_t kb = smbase + (uint32_t)(Q_SZ + s * K_SZ) * 4u;
        const uint32_t vb = smbase + (uint32_t)(Q_SZ + 2 * K_SZ + s * V_SZ) * 4u;
#pragma unroll
        for (int i = 0; i < 8; i++) {
            const int f = i * 256 + tid;
            const int r = f >> 5, c4 = (f & 31) << 2;
            cp_async16(kb + (uint32_t)(r * KST + c4) * 4u, ksrc + (size_t)r * KVDIM + c4);
            cp_async16(vb + (uint32_t)(r * VST + c4) * 4u, vsrc + (size_t)r * KVDIM + c4);
        }
        cp_commit();
    };

    issueQ();
    issueKV(0, 0);
    if (qt >= 1) issueKV(1, 1);

    // ---- wait stage 0, hoist Q fragments into registers ----
    if (qt >= 1) cp_wait<1>(); else cp_wait<0>();
    __syncthreads();

    uint32_t qF[16][4];
#pragma unroll
    for (int ks = 0; ks < 16; ks++) {
        const float* ap = Qs + rr0 * QST + (ks << 3) + c;
        qF[ks][0] = __float_as_uint(ap[0]);
        qF[ks][1] = __float_as_uint(ap[8 * QST]);
        qF[ks][2] = __float_as_uint(ap[4]);
        qF[ks][3] = __float_as_uint(ap[8 * QST + 4]);
    }
    // (Ps writes first occur after the S2 barrier of iter 0 — Qs reads are safe)

    float oreg[8][4];
#pragma unroll
    for (int n = 0; n < 8; n++)
#pragma unroll
        for (int r = 0; r < 4; r++) oreg[n][r] = 0.f;

    float m0 = -1e30f, m1 = -1e30f, l0 = 0.f, l1 = 0.f;   // replicated row state

    for (int j = 0; j <= qt; j++) {
        if (j > 0) {                      // stage j&1 arrival (iter 0 pre-waited)
            if (j < qt) cp_wait<1>(); else cp_wait<0>();
            __syncthreads();              // S1
        }
        const float* Kj = Ks + (j & 1) * K_SZ;
        const float* Vj = Vs + (j & 1) * V_SZ;

        // ---- S = Q K^T : warp tile 16x32 ----
        float sacc[4][4];
#pragma unroll
        for (int n = 0; n < 4; n++)
#pragma unroll
            for (int r = 0; r < 4; r++) sacc[n][r] = 0.f;

#pragma unroll
        for (int ks = 0; ks < 16; ks++) {
            const int k0 = ks << 3;
#pragma unroll
            for (int nt = 0; nt < 4; nt++) {
                const float* bp = Kj + (wn * 32 + nt * 8 + g) * KST + k0 + c;
                mma_tf32(sacc[nt], qF[ks][0], qF[ks][1], qF[ks][2], qF[ks][3],
                         __float_as_uint(bp[0]), __float_as_uint(bp[4]));
            }
        }

        // ---- causal mask in registers (diagonal tile only) ----
        if (j == qt) {
#pragma unroll
            for (int nt = 0; nt < 4; nt++) {
                const int cb = wn * 32 + nt * 8 + 2 * c;
                if (cb     > rr0) sacc[nt][0] = -1e30f;
                if (cb + 1 > rr0) sacc[nt][1] = -1e30f;
                if (cb     > rr1) sacc[nt][2] = -1e30f;
                if (cb + 1 > rr1) sacc[nt][3] = -1e30f;
            }
        }

        // ---- row max: registers -> bfly over c -> smem partials ----
        float rm0 = -1e30f, rm1 = -1e30f;
#pragma unroll
        for (int nt = 0; nt < 4; nt++) {
            rm0 = fmaxf(rm0, fmaxf(sacc[nt][0], sacc[nt][1]));
            rm1 = fmaxf(rm1, fmaxf(sacc[nt][2], sacc[nt][3]));
        }
        rm0 = fmaxf(rm0, __shfl_xor_sync(0xffffffffu, rm0, 1));
        rm0 = fmaxf(rm0, __shfl_xor_sync(0xffffffffu, rm0, 2));
        rm1 = fmaxf(rm1, __shfl_xor_sync(0xffffffffu, rm1, 1));
        rm1 = fmaxf(rm1, __shfl_xor_sync(0xffffffffu, rm1, 2));
        if (c == 0) {
            s_part[wn * 64 + rr0] = rm0;
            s_part[wn * 64 + rr1] = rm1;
        }
        __syncthreads();                  // S2

        // ---- combine partials, online-update m, compute corr (all threads) ----
        const float t0 = fmaxf(s_part[rr0], s_part[64 + rr0]);
        const float t1 = fmaxf(s_part[rr1], s_part[64 + rr1]);
        const float mn0 = fmaxf(m0, t0), mn1 = fmaxf(m1, t1);
        const float corr0 = __expf(m0 - mn0), corr1 = __expf(m1 - mn1);
        m0 = mn0; m1 = mn1;

        // ---- exp + tf32 round + stage P + row-sum partials ----
        float rs0 = 0.f, rs1 = 0.f;
#pragma unroll
        for (int nt = 0; nt < 4; nt++) {
            const int col = wn * 32 + nt * 8 + 2 * c;
            const float p0 = tf32r(__expf(sacc[nt][0] - mn0));
            const float p1 = tf32r(__expf(sacc[nt][1] - mn0));
            const float p2 = tf32r(__expf(sacc[nt][2] - mn1));
            const float p3 = tf32r(__expf(sacc[nt][3] - mn1));
            rs0 += p0 + p1;
            rs1 += p2 + p3;
            *(float2*)(Ps + rr0 * PST + col) = make_float2(p0, p1);
            *(float2*)(Ps + rr1 * PST + col) = make_float2(p2, p3);
        }
        rs0 += __shfl_xor_sync(0xffffffffu, rs0, 1);
        rs0 += __shfl_xor_sync(0xffffffffu, rs0, 2);
        rs1 += __shfl_xor_sync(0xffffffffu, rs1, 1);
        rs1 += __shfl_xor_sync(0xffffffffu, rs1, 2);
        if (c == 0) {
            s_psum[wn * 64 + rr0] = rs0;
            s_psum[wn * 64 + rr1] = rs1;
        }
        __syncthreads();                  // S3: Ps + psum ready

        // ---- l update + O rescale ----
        l0 = l0 * corr0 + s_psum[rr0] + s_psum[64 + rr0];
        l1 = l1 * corr1 + s_psum[rr1] + s_psum[64 + rr1];
#pragma unroll
        for (int n = 0; n < 8; n++) {
            oreg[n][0] *= corr0; oreg[n][1] *= corr0;
            oreg[n][2] *= corr1; oreg[n][3] *= corr1;
        }

        // ---- O += P @ V : warp tile 16 x 64 ----
#pragma unroll
        for (int ks = 0; ks < 8; ks++) {
            const int k0 = ks << 3;
            const float* ap = Ps + rr0 * PST + k0 + c;
            const uint32_t a0 = __float_as_uint(ap[0]);
            const uint32_t a1 = __float_as_uint(ap[8 * PST]);
            const uint32_t a2 = __float_as_uint(ap[4]);
            const uint32_t a3 = __float_as_uint(ap[8 * PST + 4]);
#pragma unroll
            for (int nt = 0; nt < 8; nt++) {
                const float* bp = Vj + (k0 + c) * VST + wn * 64 + nt * 8 + g;
                mma_tf32(oreg[nt], a0, a1, a2, a3,
                         __float_as_uint(bp[0]), __float_as_uint(bp[4 * VST]));
            }
        }
        __syncthreads();                  // S4: stage j&1 + Ps reads done

        if (j + 2 <= qt) issueKV(j + 2, j & 1);
    }

    // ---- output (l state in registers) ----
    const float inv0 = 1.f / l0;
    const float inv1 = 1.f / l1;
    const int row0 = b * Sn + qb + rr0;
#pragma unroll
    for (int nt = 0; nt < 8; nt++) {
        const int col = h * Dn + wn * 64 + nt * 8 + 2 * c;
        *(float2*)(Og + (size_t)row0 * QDIM + col) =
            make_float2(oreg[nt][0] * inv0, oreg[nt][1] * inv0);
        *(float2*)(Og + (size_t)(row0 + 8) * QDIM + col) =
            make_float2(oreg[nt][2] * inv1, oreg[nt][3] * inv1);
    }
}

// ---------------------------------------------------------------------------
// Launch pipeline
// ---------------------------------------------------------------------------
extern "C" void kernel_launch(void* const* d_in, const int* in_sizes, int n_in,
                              void* d_out, int out_size) {
    const float* x  = (const float*)d_in[0];
    const float* cs = (const float*)d_in[1];
    const float* sn = (const float*)d_in[2];
    const float* Wq = (const float*)d_in[3];
    const float* Wk = (const float*)d_in[4];
    const float* Wv = (const float*)d_in[5];
    const float* Wo = (const float*)d_in[6];
    float* out = (float*)d_out;

    float *Qp, *Kp, *Vp, *Op, *Xr, *Wqr, *Wkr, *Wvr, *Wor;
    cudaGetSymbolAddress((void**)&Qp,  g_Q);
    cudaGetSymbolAddress((void**)&Kp,  g_K);
    cudaGetSymbolAddress((void**)&Vp,  g_V);
    cudaGetSymbolAddress((void**)&Op,  g_O);
    cudaGetSymbolAddress((void**)&Xr,  g_Xr);
    cudaGetSymbolAddress((void**)&Wqr, g_Wqr);
    cudaGetSymbolAddress((void**)&Wkr, g_Wkr);
    cudaGetSymbolAddress((void**)&Wvr, g_Wvr);
    cudaGetSymbolAddress((void**)&Wor, g_Wor);

    cudaFuncSetAttribute(flash_tc_kernel,
                         cudaFuncAttributeMaxDynamicSharedMemorySize, FLASH_SMEM);
    cudaFuncSetAttribute(qkv_gemm_tf32,
                         cudaFuncAttributeMaxDynamicSharedMemorySize, GEMM_SMEM);
    cudaFuncSetAttribute(gemm_tf32,
                         cudaFuncAttributeMaxDynamicSharedMemorySize, GEMM_SMEM);

    const int TPB = 256;
    round_tf32_kernel<<<(NTOK * HIDn / 4 + TPB - 1) / TPB, TPB>>>(x,  Xr,  NTOK * HIDn / 4);
    round_tf32_kernel<<<(HIDn * QDIM / 4 + TPB - 1) / TPB, TPB>>>(Wq, Wqr, HIDn * QDIM / 4);
    round_tf32_kernel<<<(HIDn * KVDIM / 4 + TPB - 1) / TPB, TPB>>>(Wk, Wkr, HIDn * KVDIM / 4);
    round_tf32_kernel<<<(HIDn * KVDIM / 4 + TPB - 1) / TPB, TPB>>>(Wv, Wvr, HIDn * KVDIM / 4);
    round_tf32_kernel<<<(QDIM * HIDn / 4 + TPB - 1) / TPB, TPB>>>(Wo, Wor, QDIM * HIDn / 4);

    // QKV projections (tf32 tensor cores)
    qkv_gemm_tf32<<<dim3(24, NTOK / 128), 256, GEMM_SMEM>>>(Xr, Wqr, Wkr, Wvr, Qp, Kp, Vp);

    // RoPE + 1/sqrt(D) fold + tf32 rounding of Q,K,V
    rope_round_kernel<<<dim3(NTOK, Hn + Gn + Gn), 64>>>(Qp, Kp, Vp, cs, sn);

    // Flash attention on tensor cores (parallel register softmax)
    flash_tc_kernel<<<dim3(Sn / BQ, Hn, Bn), 256, FLASH_SMEM>>>(Qp, Kp, Vp, Op);

    // Round O, then output projection
    round_tf32_kernel<<<(NTOK * QDIM / 4 + TPB - 1) / TPB, TPB>>>(Op, Op, NTOK * QDIM / 4);
    gemm_tf32<<<dim3(HIDn / 128, NTOK / 128), 256, GEMM_SMEM>>>(Op, Wor, out, HIDn, QDIM);
}

// round 7
// speedup vs baseline: 3.5358x; 1.0039x over previous
#include <cuda_runtime.h>
#include <math.h>
#include <stdint.h>

// Problem constants
#define Bn   2
#define Sn   2048
#define HIDn 2048
#define Hn   16
#define Gn   4
#define Dn   128
#define NTOK (Bn * Sn)      // 4096
#define QDIM (Hn * Dn)      // 2048
#define KVDIM (Gn * Dn)     // 512

// Flash tiling
#define BQ 64
#define BK 64

// ---------------------------------------------------------------------------
// Scratch (__device__ globals per allocation-free rule)
// ---------------------------------------------------------------------------
__device__ float g_Q[NTOK * QDIM];
__device__ float g_K[NTOK * KVDIM];
__device__ float g_V[NTOK * KVDIM];
__device__ float g_O[NTOK * QDIM];
__device__ float g_Xr[NTOK * HIDn];
__device__ float g_Wqr[HIDn * QDIM];
__device__ float g_Wkr[HIDn * KVDIM];
__device__ float g_Wvr[HIDn * KVDIM];
__device__ float g_Wor[QDIM * HIDn];

// ---------------------------------------------------------------------------
// tf32 round + rounding pass
// ---------------------------------------------------------------------------
__device__ __forceinline__ float tf32r(float x) {
    uint32_t u;
    asm("cvt.rna.tf32.f32 %0, %1;" : "=r"(u) : "f"(x));
    return __uint_as_float(u);
}

__global__ void round_tf32_kernel(const float* __restrict__ in,
                                  float* __restrict__ out, int n4) {
    int i = blockIdx.x * blockDim.x + threadIdx.x;
    if (i < n4) {
        float4 v = ((const float4*)in)[i];
        v.x = tf32r(v.x); v.y = tf32r(v.y); v.z = tf32r(v.z); v.w = tf32r(v.w);
        ((float4*)out)[i] = v;
    }
}

// ---------------------------------------------------------------------------
// cp.async helpers
// ---------------------------------------------------------------------------
__device__ __forceinline__ void cp_async16(uint32_t dst, const void* src) {
    asm volatile("cp.async.cg.shared.global [%0], [%1], 16;" :: "r"(dst), "l"(src));
}
__device__ __forceinline__ void cp_commit() {
    asm volatile("cp.async.commit_group;");
}
template <int N>
__device__ __forceinline__ void cp_wait() {
    asm volatile("cp.async.wait_group %0;" :: "n"(N));
}

// ---------------------------------------------------------------------------
// mma.m16n8k8 tf32 helper
// ---------------------------------------------------------------------------
__device__ __forceinline__
void mma_tf32(float* d, uint32_t a0, uint32_t a1, uint32_t a2, uint32_t a3,
              uint32_t b0, uint32_t b1) {
    asm volatile(
        "mma.sync.aligned.m16n8k8.row.col.f32.tf32.tf32.f32 "
        "{%0,%1,%2,%3}, {%4,%5,%6,%7}, {%8,%9}, {%0,%1,%2,%3};"
        : "+f"(d[0]), "+f"(d[1]), "+f"(d[2]), "+f"(d[3])
        : "r"(a0), "r"(a1), "r"(a2), "r"(a3), "r"(b0), "r"(b1));
}

// ---------------------------------------------------------------------------
// tf32 mma.sync GEMM, CTA tile 128x256, warp tile 64x64 (8 warps, 2x4),
// BK=32, 3-stage cp.async pipeline. C = A[M,K] @ B[K,N] (both K-major gmem).
// A smem [128][36] (bank 4g+c), B smem [32][264] (bank 8c+8j+g) — both
// conflict-free for the m16n8k8 fragment loads. 128 accumulator regs/thread.
// ---------------------------------------------------------------------------
#define AS_ST 36
#define BS_ST 264
#define A_SZ (128 * AS_ST)              // 4608 floats
#define B_SZ (32 * BS_ST)               // 8448 floats
#define STG_SZ (A_SZ + B_SZ)            // 13056 floats = 52224 B
#define NSTG 3
#define GEMM_SMEM (NSTG * STG_SZ * (int)sizeof(float))   // 156672 B

__device__ __forceinline__
void gemm_tf32_body(const float* __restrict__ A, const float* __restrict__ B,
                    float* __restrict__ C, int Ncols, int colbase, int K, int by) {
    extern __shared__ float sm[];
    const int tid  = threadIdx.x;
    const int w    = tid >> 5, lane = tid & 31;
    const int wm   = w >> 2,   wn   = w & 3;     // 2 x 4 warp grid
    const int g    = lane >> 2, c   = lane & 3;

    const uint32_t smbase = (uint32_t)__cvta_generic_to_shared(sm);

    float d[4][8][4];
#pragma unroll
    for (int i = 0; i < 4; i++)
#pragma unroll
        for (int j = 0; j < 8; j++)
#pragma unroll
            for (int r = 0; r < 4; r++) d[i][j][r] = 0.f;

    const int niter = K / 32;
    const float* Abase = A + (size_t)(by * 128) * K;
    const float* Bbase = B + colbase;

    auto issue = [&](int it) {
        const int s = it % NSTG;
        const uint32_t sAu = smbase + (uint32_t)(s * STG_SZ) * 4u;
        const uint32_t sBu = sAu + (uint32_t)A_SZ * 4u;
        const float* Ag = Abase + it * 32;
        const float* Bg = Bbase + (size_t)(it * 32) * Ncols;
#pragma unroll
        for (int i = 0; i < 4; i++) {            // A: 1024 16B units
            const int f = i * 256 + tid;
            const int m = f >> 3, kc = (f & 7) << 2;
            cp_async16(sAu + (uint32_t)(m * AS_ST + kc) * 4u,
                       Ag + (size_t)m * K + kc);
        }
#pragma unroll
        for (int i = 0; i < 8; i++) {            // B: 2048 16B units
            const int f = i * 256 + tid;
            const int kb = f >> 6, nc = (f & 63) << 2;
            cp_async16(sBu + (uint32_t)(kb * BS_ST + nc) * 4u,
                       Bg + (size_t)kb * Ncols + nc);
        }
        cp_commit();
    };

    issue(0); issue(1); issue(2);

    for (int it = 0; it < niter; it++) {
        cp_wait<NSTG - 1>();                     // chunk `it` resident
        __syncthreads();

        const float* sA = sm + (it % NSTG) * STG_SZ;
        const float* sB = sA + A_SZ;

#pragma unroll
        for (int s = 0; s < 4; s++) {            // 4 k8-steps
            const int k0 = s << 3;
            uint32_t aF[4][4], bF[8][2];
#pragma unroll
            for (int i = 0; i < 4; i++) {
                const float* ap = sA + (wm * 64 + i * 16 + g) * AS_ST + k0 + c;
                aF[i][0] = __float_as_uint(ap[0]);
                aF[i][1] = __float_as_uint(ap[8 * AS_ST]);
                aF[i][2] = __float_as_uint(ap[4]);
                aF[i][3] = __float_as_uint(ap[8 * AS_ST + 4]);
            }
#pragma unroll
            for (int j = 0; j < 8; j++) {
                const float* bp = sB + (k0 + c) * BS_ST + wn * 64 + j * 8 + g;
                bF[j][0] = __float_as_uint(bp[0]);
                bF[j][1] = __float_as_uint(bp[4 * BS_ST]);
            }
#pragma unroll
            for (int i = 0; i < 4; i++)
#pragma unroll
                for (int j = 0; j < 8; j++)
                    mma_tf32(d[i][j], aF[i][0], aF[i][1], aF[i][2], aF[i][3],
                             bF[j][0], bF[j][1]);
        }
        __syncthreads();                         // all reads of stage done
        if (it + NSTG < niter) issue(it + NSTG);
    }

    // ---- epilogue: direct float2 stores ----
#pragma unroll
    for (int i = 0; i < 4; i++) {
        const int r0 = by * 128 + wm * 64 + i * 16 + g;
#pragma unroll
        for (int j = 0; j < 8; j++) {
            const int col = colbase + wn * 64 + j * 8 + c * 2;
            *(float2*)(C + (size_t)r0 * Ncols + col)       = make_float2(d[i][j][0], d[i][j][1]);
            *(float2*)(C + (size_t)(r0 + 8) * Ncols + col) = make_float2(d[i][j][2], d[i][j][3]);
        }
    }
}

// Fused QKV: grid.x = 12 (8 Q col-tiles of 256 + 2 K + 2 V), grid.y = 32
__global__ __launch_bounds__(256, 1)
void qkv_gemm_tf32(const float* __restrict__ x,
                   const float* __restrict__ Wq, const float* __restrict__ Wk,
                   const float* __restrict__ Wv,
                   float* __restrict__ Q, float* __restrict__ K, float* __restrict__ V) {
    const int bx = blockIdx.x;
    const float* B; float* C; int Ncols; int cx;
    if (bx < 8)       { B = Wq; C = Q; Ncols = QDIM;  cx = bx; }
    else if (bx < 10) { B = Wk; C = K; Ncols = KVDIM; cx = bx - 8; }
    else              { B = Wv; C = V; Ncols = KVDIM; cx = bx - 10; }
    gemm_tf32_body(x, B, C, Ncols, cx * 256, HIDn, blockIdx.y);
}

__global__ __launch_bounds__(256, 1)
void gemm_tf32(const float* __restrict__ A, const float* __restrict__ B,
               float* __restrict__ C, int Ncols, int K) {
    gemm_tf32_body(A, B, C, Ncols, blockIdx.x * 256, K, blockIdx.y);
}

// ---------------------------------------------------------------------------
// RoPE + tf32 pre-rounding (unchanged, passing)
// ---------------------------------------------------------------------------
__global__ void rope_round_kernel(float* __restrict__ Q, float* __restrict__ K,
                                  float* __restrict__ V,
                                  const float* __restrict__ cs,
                                  const float* __restrict__ sn) {
    const int t = blockIdx.x;
    const int h = blockIdx.y;
    const int d = threadIdx.x;        // 0..63
    const int s = t & (Sn - 1);

    if (h >= Hn + Gn) {               // V: round only
        float* p = V + (size_t)t * KVDIM + (h - Hn - Gn) * Dn;
        p[d]      = tf32r(p[d]);
        p[d + 64] = tf32r(p[d + 64]);
        return;
    }
    const float c1 = cs[s * Dn + d],      s1 = sn[s * Dn + d];
    const float c2 = cs[s * Dn + d + 64], s2 = sn[s * Dn + d + 64];
    const bool isQ = (h < Hn);
    float* p = isQ ? (Q + (size_t)t * QDIM + h * Dn)
                   : (K + (size_t)t * KVDIM + (h - Hn) * Dn);
    const float sc = isQ ? 0.08838834764831845f : 1.0f;   // 1/sqrt(128)
    const float a = p[d], b = p[d + 64];
    p[d]      = tf32r((a * c1 - b * s1) * sc);
    p[d + 64] = tf32r((b * c2 + a * s2) * sc);
}

// ---------------------------------------------------------------------------
// Causal GQA flash attention (unchanged, passing R5 kernel)
// ---------------------------------------------------------------------------
#define QST 132
#define KST 132
#define VST 136
#define PST 68
#define Q_SZ  (BQ * QST)
#define K_SZ  (BK * KST)
#define V_SZ  (BK * VST)
#define PART_OFF (Q_SZ + 2 * K_SZ + 2 * V_SZ)
#define FLASH_SMEM ((PART_OFF + 256) * (int)sizeof(float))  // 172,032 B

__global__ __launch_bounds__(256)
void flash_tc_kernel(const float* __restrict__ Qg, const float* __restrict__ Kg,
                     const float* __restrict__ Vg, float* __restrict__ Og) {
    extern __shared__ float smf[];
    float* Qs = smf;
    float* Ps = smf;
    float* Ks = smf + Q_SZ;
    float* Vs = smf + Q_SZ + 2 * K_SZ;
    float* s_part = smf + PART_OFF;
    float* s_psum = s_part + 128;
    const uint32_t smbase = (uint32_t)__cvta_generic_to_shared(smf);

    const int tid = threadIdx.x;
    const int w = tid >> 5, lane = tid & 31;
    const int g = lane >> 2, c = lane & 3;
    const int wm = w & 3;
    const int wn = w >> 2;

    const int h = blockIdx.y;
    const int b = blockIdx.z;
    const int qt = (int)gridDim.x - 1 - (int)blockIdx.x;
    const int qb = qt * BQ;
    const int gh = h >> 2;

    const int rr0 = wm * 16 + g;
    const int rr1 = rr0 + 8;

    auto issueQ = [&]() {
        const float* src = Qg + ((size_t)(b * Sn + qb)) * QDIM + h * Dn;
#pragma unroll
        for (int i = 0; i < 8; i++) {
            const int f = i * 256 + tid;
            const int r = f >> 5, c4 = (f & 31) << 2;
            cp_async16(smbase + (uint32_t)(r * QST + c4) * 4u,
                       src + (size_t)r * QDIM + c4);
        }
    };
    auto issueKV = [&](int j, int s) {
        const float* ksrc = Kg + ((size_t)(b * Sn + j * BK)) * KVDIM + gh * Dn;
        const float* vsrc = Vg + ((size_t)(b * Sn + j * BK)) * KVDIM + gh * Dn;
        const uint32_t kb = smbase + (uint32_t)(Q_SZ + s * K_SZ) * 4u;
        const uint32_t vb = smbase + (uint32_t)(Q_SZ + 2 * K_SZ + s * V_SZ) * 4u;
#pragma unroll
        for (int i = 0; i < 8; i++) {
            const int f = i * 256 + tid;
            const int r = f >> 5, c4 = (f & 31) << 2;
            cp_async16(kb + (uint32_t)(r * KST + c4) * 4u, ksrc + (size_t)r * KVDIM + c4);
            cp_async16(vb + (uint32_t)(r * VST + c4) * 4u, vsrc + (size_t)r * KVDIM + c4);
        }
        cp_commit();
    };

    issueQ();
    issueKV(0, 0);
    if (qt >= 1) issueKV(1, 1);

    if (qt >= 1) cp_wait<1>(); else cp_wait<0>();
    __syncthreads();

    uint32_t qF[16][4];
#pragma unroll
    for (int ks = 0; ks < 16; ks++) {
        const float* ap = Qs + rr0 * QST + (ks << 3) + c;
        qF[ks][0] = __float_as_uint(ap[0]);
        qF[ks][1] = __float_as_uint(ap[8 * QST]);
        qF[ks][2] = __float_as_uint(ap[4]);
        qF[ks][3] = __float_as_uint(ap[8 * QST + 4]);
    }

    float oreg[8][4];
#pragma unroll
    for (int n = 0; n < 8; n++)
#pragma unroll
        for (int r = 0; r < 4; r++) oreg[n][r] = 0.f;

    float m0 = -1e30f, m1 = -1e30f, l0 = 0.f, l1 = 0.f;

    for (int j = 0; j <= qt; j++) {
        if (j > 0) {
            if (j < qt) cp_wait<1>(); else cp_wait<0>();
            __syncthreads();
        }
        const float* Kj = Ks + (j & 1) * K_SZ;
        const float* Vj = Vs + (j & 1) * V_SZ;

        float sacc[4][4];
#pragma unroll
        for (int n = 0; n < 4; n++)
#pragma unroll
            for (int r = 0; r < 4; r++) sacc[n][r] = 0.f;

#pragma unroll
        for (int ks = 0; ks < 16; ks++) {
            const int k0 = ks << 3;
#pragma unroll
            for (int nt = 0; nt < 4; nt++) {
                const float* bp = Kj + (wn * 32 + nt * 8 + g) * KST + k0 + c;
                mma_tf32(sacc[nt], qF[ks][0], qF[ks][1], qF[ks][2], qF[ks][3],
                         __float_as_uint(bp[0]), __float_as_uint(bp[4]));
            }
        }

        if (j == qt) {
#pragma unroll
            for (int nt = 0; nt < 4; nt++) {
                const int cb = wn * 32 + nt * 8 + 2 * c;
                if (cb     > rr0) sacc[nt][0] = -1e30f;
                if (cb + 1 > rr0) sacc[nt][1] = -1e30f;
                if (cb     > rr1) sacc[nt][2] = -1e30f;
                if (cb + 1 > rr1) sacc[nt][3] = -1e30f;
            }
        }

        float rm0 = -1e30f, rm1 = -1e30f;
#pragma unroll
        for (int nt = 0; nt < 4; nt++) {
            rm0 = fmaxf(rm0, fmaxf(sacc[nt][0], sacc[nt][1]));
            rm1 = fmaxf(rm1, fmaxf(sacc[nt][2], sacc[nt][3]));
        }
        rm0 = fmaxf(rm0, __shfl_xor_sync(0xffffffffu, rm0, 1));
        rm0 = fmaxf(rm0, __shfl_xor_sync(0xffffffffu, rm0, 2));
        rm1 = fmaxf(rm1, __shfl_xor_sync(0xffffffffu, rm1, 1));
        rm1 = fmaxf(rm1, __shfl_xor_sync(0xffffffffu, rm1, 2));
        if (c == 0) {
            s_part[wn * 64 + rr0] = rm0;
            s_part[wn * 64 + rr1] = rm1;
        }
        __syncthreads();

        const float t0 = fmaxf(s_part[rr0], s_part[64 + rr0]);
        const float t1 = fmaxf(s_part[rr1], s_part[64 + rr1]);
        const float mn0 = fmaxf(m0, t0), mn1 = fmaxf(m1, t1);
        const float corr0 = __expf(m0 - mn0), corr1 = __expf(m1 - mn1);
        m0 = mn0; m1 = mn1;

        float rs0 = 0.f, rs1 = 0.f;
#pragma unroll
        for (int nt = 0; nt < 4; nt++) {
            const int col = wn * 32 + nt * 8 + 2 * c;
            const float p0 = tf32r(__expf(sacc[nt][0] - mn0));
            const float p1 = tf32r(__expf(sacc[nt][1] - mn0));
            const float p2 = tf32r(__expf(sacc[nt][2] - mn1));
            const float p3 = tf32r(__expf(sacc[nt][3] - mn1));
            rs0 += p0 + p1;
            rs1 += p2 + p3;
            *(float2*)(Ps + rr0 * PST + col) = make_float2(p0, p1);
            *(float2*)(Ps + rr1 * PST + col) = make_float2(p2, p3);
        }
        rs0 += __shfl_xor_sync(0xffffffffu, rs0, 1);
        rs0 += __shfl_xor_sync(0xffffffffu, rs0, 2);
        rs1 += __shfl_xor_sync(0xffffffffu, rs1, 1);
        rs1 += __shfl_xor_sync(0xffffffffu, rs1, 2);
        if (c == 0) {
            s_psum[wn * 64 + rr0] = rs0;
            s_psum[wn * 64 + rr1] = rs1;
        }
        __syncthreads();

        l0 = l0 * corr0 + s_psum[rr0] + s_psum[64 + rr0];
        l1 = l1 * corr1 + s_psum[rr1] + s_psum[64 + rr1];
#pragma unroll
        for (int n = 0; n < 8; n++) {
            oreg[n][0] *= corr0; oreg[n][1] *= corr0;
            oreg[n][2] *= corr1; oreg[n][3] *= corr1;
        }

#pragma unroll
        for (int ks = 0; ks < 8; ks++) {
            const int k0 = ks << 3;
            const float* ap = Ps + rr0 * PST + k0 + c;
            const uint32_t a0 = __float_as_uint(ap[0]);
            const uint32_t a1 = __float_as_uint(ap[8 * PST]);
            const uint32_t a2 = __float_as_uint(ap[4]);
            const uint32_t a3 = __float_as_uint(ap[8 * PST + 4]);
#pragma unroll
            for (int nt = 0; nt < 8; nt++) {
                const float* bp = Vj + (k0 + c) * VST + wn * 64 + nt * 8 + g;
                mma_tf32(oreg[nt], a0, a1, a2, a3,
                         __float_as_uint(bp[0]), __float_as_uint(bp[4 * VST]));
            }
        }
        __syncthreads();

        if (j + 2 <= qt) issueKV(j + 2, j & 1);
    }

    const float inv0 = 1.f / l0;
    const float inv1 = 1.f / l1;
    const int row0 = b * Sn + qb + rr0;
#pragma unroll
    for (int nt = 0; nt < 8; nt++) {
        const int col = h * Dn + wn * 64 + nt * 8 + 2 * c;
        *(float2*)(Og + (size_t)row0 * QDIM + col) =
            make_float2(oreg[nt][0] * inv0, oreg[nt][1] * inv0);
        *(float2*)(Og + (size_t)(row0 + 8) * QDIM + col) =
            make_float2(oreg[nt][2] * inv1, oreg[nt][3] * inv1);
    }
}

// ---------------------------------------------------------------------------
// Launch pipeline
// ---------------------------------------------------------------------------
extern "C" void kernel_launch(void* const* d_in, const int* in_sizes, int n_in,
                              void* d_out, int out_size) {
    const float* x  = (const float*)d_in[0];
    const float* cs = (const float*)d_in[1];
    const float* sn = (const float*)d_in[2];
    const float* Wq = (const float*)d_in[3];
    const float* Wk = (const float*)d_in[4];
    const float* Wv = (const float*)d_in[5];
    const float* Wo = (const float*)d_in[6];
    float* out = (float*)d_out;

    float *Qp, *Kp, *Vp, *Op, *Xr, *Wqr, *Wkr, *Wvr, *Wor;
    cudaGetSymbolAddress((void**)&Qp,  g_Q);
    cudaGetSymbolAddress((void**)&Kp,  g_K);
    cudaGetSymbolAddress((void**)&Vp,  g_V);
    cudaGetSymbolAddress((void**)&Op,  g_O);
    cudaGetSymbolAddress((void**)&Xr,  g_Xr);
    cudaGetSymbolAddress((void**)&Wqr, g_Wqr);
    cudaGetSymbolAddress((void**)&Wkr, g_Wkr);
    cudaGetSymbolAddress((void**)&Wvr, g_Wvr);
    cudaGetSymbolAddress((void**)&Wor, g_Wor);

    cudaFuncSetAttribute(flash_tc_kernel,
                         cudaFuncAttributeMaxDynamicSharedMemorySize, FLASH_SMEM);
    cudaFuncSetAttribute(qkv_gemm_tf32,
                         cudaFuncAttributeMaxDynamicSharedMemorySize, GEMM_SMEM);
    cudaFuncSetAttribute(gemm_tf32,
                         cudaFuncAttributeMaxDynamicSharedMemorySize, GEMM_SMEM);

    const int TPB = 256;
    round_tf32_kernel<<<(NTOK * HIDn / 4 + TPB - 1) / TPB, TPB>>>(x,  Xr,  NTOK * HIDn / 4);
    round_tf32_kernel<<<(HIDn * QDIM / 4 + TPB - 1) / TPB, TPB>>>(Wq, Wqr, HIDn * QDIM / 4);
    round_tf32_kernel<<<(HIDn * KVDIM / 4 + TPB - 1) / TPB, TPB>>>(Wk, Wkr, HIDn * KVDIM / 4);
    round_tf32_kernel<<<(HIDn * KVDIM / 4 + TPB - 1) / TPB, TPB>>>(Wv, Wvr, HIDn * KVDIM / 4);
    round_tf32_kernel<<<(QDIM * HIDn / 4 + TPB - 1) / TPB, TPB>>>(Wo, Wor, QDIM * HIDn / 4);

    // QKV projections (tf32 mma.sync, 128x256 CTA tiles)
    qkv_gemm_tf32<<<dim3(12, NTOK / 128), 256, GEMM_SMEM>>>(Xr, Wqr, Wkr, Wvr, Qp, Kp, Vp);

    // RoPE + 1/sqrt(D) fold + tf32 rounding
    rope_round_kernel<<<dim3(NTOK, Hn + Gn + Gn), 64>>>(Qp, Kp, Vp, cs, sn);

    // Flash attention (tf32 mma.sync, parallel register softmax)
    flash_tc_kernel<<<dim3(Sn / BQ, Hn, Bn), 256, FLASH_SMEM>>>(Qp, Kp, Vp, Op);

    // Round O, then output projection
    round_tf32_kernel<<<(NTOK * QDIM / 4 + TPB - 1) / TPB, TPB>>>(Op, Op, NTOK * QDIM / 4);
    gemm_tf32<<<dim3(HIDn / 256, NTOK / 128), 256, GEMM_SMEM>>>(Op, Wor, out, HIDn, QDIM);
}

// round 8
// speedup vs baseline: 4.7633x; 1.3472x over previous
#include <cuda_runtime.h>
#include <cuda_fp16.h>
#include <math.h>
#include <stdint.h>

// Problem constants
#define Bn   2
#define Sn   2048
#define HIDn 2048
#define Hn   16
#define Gn   4
#define Dn   128
#define NTOK (Bn * Sn)      // 4096
#define QDIM (Hn * Dn)      // 2048
#define KVDIM (Gn * Dn)     // 512

// Flash tiling
#define BQ 64
#define BK 64

// ---------------------------------------------------------------------------
// Scratch (__device__ globals per allocation-free rule)
// ---------------------------------------------------------------------------
__device__ float  g_Q[NTOK * QDIM];
__device__ float  g_K[NTOK * KVDIM];
__device__ float  g_V[NTOK * KVDIM];
__device__ float  g_O[NTOK * QDIM];
__device__ __half g_Xh[NTOK * HIDn];
__device__ __half g_Oh[NTOK * QDIM];
__device__ __half g_Wqt[QDIM * HIDn];    // transposed [N][K] fp16
__device__ __half g_Wkt[KVDIM * HIDn];
__device__ __half g_Wvt[KVDIM * HIDn];
__device__ __half g_Wot[HIDn * QDIM];

// ---------------------------------------------------------------------------
// tf32 round helper (flash path)
// ---------------------------------------------------------------------------
__device__ __forceinline__ float tf32r(float x) {
    uint32_t u;
    asm("cvt.rna.tf32.f32 %0, %1;" : "=r"(u) : "f"(x));
    return __uint_as_float(u);
}

// fp32 -> fp16 conversion pass (rn)
__global__ void f32_to_h_kernel(const float* __restrict__ in,
                                __half* __restrict__ out, int n4) {
    int i = blockIdx.x * blockDim.x + threadIdx.x;
    if (i < n4) {
        float4 v = ((const float4*)in)[i];
        __half2* o = (__half2*)out + i * 2;
        o[0] = __floats2half2_rn(v.x, v.y);
        o[1] = __floats2half2_rn(v.z, v.w);
    }
}

// Transpose + fp16 convert: in[R][C] fp32 -> out[C][R] fp16
__global__ void transpose_h_kernel(const float* __restrict__ in,
                                   __half* __restrict__ out, int R, int C) {
    __shared__ float t[32][33];
    const int r0 = blockIdx.y * 32, c0 = blockIdx.x * 32;
#pragma unroll
    for (int i = threadIdx.y; i < 32; i += 8)
        t[i][threadIdx.x] = in[(size_t)(r0 + i) * C + c0 + threadIdx.x];
    __syncthreads();
#pragma unroll
    for (int i = threadIdx.y; i < 32; i += 8)
        out[(size_t)(c0 + i) * R + r0 + threadIdx.x] = __float2half_rn(t[threadIdx.x][i]);
}

// ---------------------------------------------------------------------------
// cp.async helpers
// ---------------------------------------------------------------------------
__device__ __forceinline__ void cp_async16(uint32_t dst, const void* src) {
    asm volatile("cp.async.cg.shared.global [%0], [%1], 16;" :: "r"(dst), "l"(src));
}
__device__ __forceinline__ void cp_commit() {
    asm volatile("cp.async.commit_group;");
}
template <int N>
__device__ __forceinline__ void cp_wait() {
    asm volatile("cp.async.wait_group %0;" :: "n"(N));
}

// ---------------------------------------------------------------------------
// mma helpers
// ---------------------------------------------------------------------------
__device__ __forceinline__
void mma_tf32(float* d, uint32_t a0, uint32_t a1, uint32_t a2, uint32_t a3,
              uint32_t b0, uint32_t b1) {
    asm volatile(
        "mma.sync.aligned.m16n8k8.row.col.f32.tf32.tf32.f32 "
        "{%0,%1,%2,%3}, {%4,%5,%6,%7}, {%8,%9}, {%0,%1,%2,%3};"
        : "+f"(d[0]), "+f"(d[1]), "+f"(d[2]), "+f"(d[3])
        : "r"(a0), "r"(a1), "r"(a2), "r"(a3), "r"(b0), "r"(b1));
}
__device__ __forceinline__
void mma_f16(float* d, uint32_t a0, uint32_t a1, uint32_t a2, uint32_t a3,
             uint32_t b0, uint32_t b1) {
    asm volatile(
        "mma.sync.aligned.m16n8k16.row.col.f32.f16.f16.f32 "
        "{%0,%1,%2,%3}, {%4,%5,%6,%7}, {%8,%9}, {%0,%1,%2,%3};"
        : "+f"(d[0]), "+f"(d[1]), "+f"(d[2]), "+f"(d[3])
        : "r"(a0), "r"(a1), "r"(a2), "r"(a3), "r"(b0), "r"(b1));
}

// ---------------------------------------------------------------------------
// fp16 mma.sync GEMM: C[fp32] = A[M,K](h) @ Bt[N,K](h)^T
// CTA tile 128x256, warp tile 64x64 (8 warps 2x4), BK=64, 3-stage cp.async.
// A smem [128][72]h, B smem [256][72]h: word-stride 36 == 4 (mod 32) ->
// fragment banks 4g+c, conflict-free. cp.async store thread->unit permutation
// u=((f&7)+row)&7 makes each 8-lane STS phase hit 8 distinct bank groups.
// ---------------------------------------------------------------------------
#define HA_ST 72                        // halves per row
#define HA_SZ (128 * HA_ST)             // 9216 halves
#define HB_SZ (256 * HA_ST)             // 18432 halves
#define HSTG_B ((HA_SZ + HB_SZ) * 2)    // 55296 bytes / stage
#define HNSTG 3
#define HGEMM_SMEM (HNSTG * HSTG_B)     // 165888 B

__device__ __forceinline__
void hgemm_body(const __half* __restrict__ A, const __half* __restrict__ Bt,
                float* __restrict__ C, int Ncols, int colbase, int K, int by) {
    extern __shared__ char hsm[];
    const int tid  = threadIdx.x;
    const int w    = tid >> 5, lane = tid & 31;
    const int wm   = w >> 2,   wn   = w & 3;     // 2 x 4 warp grid
    const int g    = lane >> 2, c   = lane & 3;

    const uint32_t smbase = (uint32_t)__cvta_generic_to_shared(hsm);

    float d[4][8][4];
#pragma unroll
    for (int i = 0; i < 4; i++)
#pragma unroll
        for (int j = 0; j < 8; j++)
#pragma unroll
            for (int r = 0; r < 4; r++) d[i][j][r] = 0.f;

    const int niter = K / 64;                    // 32
    const __half* Abase = A + (size_t)(by * 128) * K;
    const __half* Bbase = Bt + (size_t)colbase * K;

    auto issue = [&](int it) {
        const int s = it % HNSTG;
        const uint32_t aB = smbase + (uint32_t)(s * HSTG_B);
        const uint32_t bB = aB + (uint32_t)(HA_SZ * 2);
        const __half* Ag = Abase + it * 64;
        const __half* Bg = Bbase + it * 64;
#pragma unroll
        for (int i = 0; i < 4; i++) {            // A: 1024 16B units
            const int f = i * 256 + tid;
            const int row = f >> 3;
            const int u = ((f & 7) + row) & 7;   // bank-phase permutation
            cp_async16(aB + (uint32_t)(row * 144 + u * 16),
                       Ag + (size_t)row * K + u * 8);
        }
#pragma unroll
        for (int i = 0; i < 8; i++) {            // B: 2048 16B units
            const int f = i * 256 + tid;
            const int row = f >> 3;
            const int u = ((f & 7) + row) & 7;
            cp_async16(bB + (uint32_t)(row * 144 + u * 16),
                       Bg + (size_t)row * K + u * 8);
        }
        cp_commit();
    };

    issue(0); issue(1); issue(2);

    for (int it = 0; it < niter; it++) {
        cp_wait<HNSTG - 1>();
        __syncthreads();

        const __half* sA = (const __half*)(hsm + (it % HNSTG) * HSTG_B);
        const __half* sB = sA + HA_SZ;

#pragma unroll
        for (int s = 0; s < 4; s++) {            // 4 k16-steps per BK=64
            const int kh = s * 16 + 2 * c;
            uint32_t aF[4][4], bF[8][2];
#pragma unroll
            for (int i = 0; i < 4; i++) {
                const __half* ap = sA + (wm * 64 + i * 16 + g) * HA_ST + kh;
                aF[i][0] = *(const uint32_t*)(ap);                 // row g,   k 2c..2c+1
                aF[i][1] = *(const uint32_t*)(ap + 8 * HA_ST);     // row g+8, same k
                aF[i][2] = *(const uint32_t*)(ap + 8);             // row g,   k +8
                aF[i][3] = *(const uint32_t*)(ap + 8 * HA_ST + 8); // row g+8, k +8
            }
#pragma unroll
            for (int j = 0; j < 8; j++) {
                const __half* bp = sB + (wn * 64 + j * 8 + g) * HA_ST + kh;
                bF[j][0] = *(const uint32_t*)(bp);                 // n g, k 2c..2c+1
                bF[j][1] = *(const uint32_t*)(bp + 8);             // n g, k +8
            }
#pragma unroll
            for (int i = 0; i < 4; i++)
#pragma unroll
                for (int j = 0; j < 8; j++)
                    mma_f16(d[i][j], aF[i][0], aF[i][1], aF[i][2], aF[i][3],
                            bF[j][0], bF[j][1]);
        }
        __syncthreads();
        if (it + HNSTG < niter) issue(it + HNSTG);
    }

    // ---- epilogue: direct float2 stores ----
#pragma unroll
    for (int i = 0; i < 4; i++) {
        const int r0 = by * 128 + wm * 64 + i * 16 + g;
#pragma unroll
        for (int j = 0; j < 8; j++) {
            const int col = colbase + wn * 64 + j * 8 + c * 2;
            *(float2*)(C + (size_t)r0 * Ncols + col)       = make_float2(d[i][j][0], d[i][j][1]);
            *(float2*)(C + (size_t)(r0 + 8) * Ncols + col) = make_float2(d[i][j][2], d[i][j][3]);
        }
    }
}

// Fused QKV: grid.x = 12 (8 Q col-tiles of 256 + 2 K + 2 V), grid.y = 32
__global__ __launch_bounds__(256, 1)
void qkv_hgemm(const __half* __restrict__ x,
               const __half* __restrict__ Wqt, const __half* __restrict__ Wkt,
               const __half* __restrict__ Wvt,
               float* __restrict__ Q, float* __restrict__ K, float* __restrict__ V) {
    const int bx = blockIdx.x;
    const __half* Bt; float* C; int Ncols; int cx;
    if (bx < 8)       { Bt = Wqt; C = Q; Ncols = QDIM;  cx = bx; }
    else if (bx < 10) { Bt = Wkt; C = K; Ncols = KVDIM; cx = bx - 8; }
    else              { Bt = Wvt; C = V; Ncols = KVDIM; cx = bx - 10; }
    hgemm_body(x, Bt, C, Ncols, cx * 256, HIDn, blockIdx.y);
}

__global__ __launch_bounds__(256, 1)
void wo_hgemm(const __half* __restrict__ A, const __half* __restrict__ Bt,
              float* __restrict__ C) {
    hgemm_body(A, Bt, C, HIDn, blockIdx.x * 256, QDIM, blockIdx.y);
}

// ---------------------------------------------------------------------------
// RoPE + tf32 pre-rounding (unchanged, passing)
// ---------------------------------------------------------------------------
__global__ void rope_round_kernel(float* __restrict__ Q, float* __restrict__ K,
                                  float* __restrict__ V,
                                  const float* __restrict__ cs,
                                  const float* __restrict__ sn) {
    const int t = blockIdx.x;
    const int h = blockIdx.y;
    const int d = threadIdx.x;        // 0..63
    const int s = t & (Sn - 1);

    if (h >= Hn + Gn) {               // V: round only
        float* p = V + (size_t)t * KVDIM + (h - Hn - Gn) * Dn;
        p[d]      = tf32r(p[d]);
        p[d + 64] = tf32r(p[d + 64]);
        return;
    }
    const float c1 = cs[s * Dn + d],      s1 = sn[s * Dn + d];
    const float c2 = cs[s * Dn + d + 64], s2 = sn[s * Dn + d + 64];
    const bool isQ = (h < Hn);
    float* p = isQ ? (Q + (size_t)t * QDIM + h * Dn)
                   : (K + (size_t)t * KVDIM + (h - Hn) * Dn);
    const float sc = isQ ? 0.08838834764831845f : 1.0f;   // 1/sqrt(128)
    const float a = p[d], b = p[d + 64];
    p[d]      = tf32r((a * c1 - b * s1) * sc);
    p[d + 64] = tf32r((b * c2 + a * s2) * sc);
}

// ---------------------------------------------------------------------------
// Causal GQA flash attention (unchanged, passing R5/R7 kernel)
// ---------------------------------------------------------------------------
#define QST 132
#define KST 132
#define VST 136
#define PST 68
#define Q_SZ  (BQ * QST)
#define K_SZ  (BK * KST)
#define V_SZ  (BK * VST)
#define PART_OFF (Q_SZ + 2 * K_SZ + 2 * V_SZ)
#define FLASH_SMEM ((PART_OFF + 256) * (int)sizeof(float))  // 172,032 B

__global__ __launch_bounds__(256)
void flash_tc_kernel(const float* __restrict__ Qg, const float* __restrict__ Kg,
                     const float* __restrict__ Vg, float* __restrict__ Og) {
    extern __shared__ float smf[];
    float* Qs = smf;
    float* Ps = smf;
    float* Ks = smf + Q_SZ;
    float* Vs = smf + Q_SZ + 2 * K_SZ;
    float* s_part = smf + PART_OFF;
    float* s_psum = s_part + 128;
    const uint32_t smbase = (uint32_t)__cvta_generic_to_shared(smf);

    const int tid = threadIdx.x;
    const int w = tid >> 5, lane = tid & 31;
    const int g = lane >> 2, c = lane & 3;
    const int wm = w & 3;
    const int wn = w >> 2;

    const int h = blockIdx.y;
    const int b = blockIdx.z;
    const int qt = (int)gridDim.x - 1 - (int)blockIdx.x;
    const int qb = qt * BQ;
    const int gh = h >> 2;

    const int rr0 = wm * 16 + g;
    const int rr1 = rr0 + 8;

    auto issueQ = [&]() {
        const float* src = Qg + ((size_t)(b * Sn + qb)) * QDIM + h * Dn;
#pragma unroll
        for (int i = 0; i < 8; i++) {
            const int f = i * 256 + tid;
            const int r = f >> 5, c4 = (f & 31) << 2;
            cp_async16(smbase + (uint32_t)(r * QST + c4) * 4u,
                       src + (size_t)r * QDIM + c4);
        }
    };
    auto issueKV = [&](int j, int s) {
        const float* ksrc = Kg + ((size_t)(b * Sn + j * BK)) * KVDIM + gh * Dn;
        const float* vsrc = Vg + ((size_t)(b * Sn + j * BK)) * KVDIM + gh * Dn;
        const uint32_t kb = smbase + (uint32_t)(Q_SZ + s * K_SZ) * 4u;
        const uint32_t vb = smbase + (uint32_t)(Q_SZ + 2 * K_SZ + s * V_SZ) * 4u;
#pragma unroll
        for (int i = 0; i < 8; i++) {
            const int f = i * 256 + tid;
            const int r = f >> 5, c4 = (f & 31) << 2;
            cp_async16(kb + (uint32_t)(r * KST + c4) * 4u, ksrc + (size_t)r * KVDIM + c4);
            cp_async16(vb + (uint32_t)(r * VST + c4) * 4u, vsrc + (size_t)r * KVDIM + c4);
        }
        cp_commit();
    };

    issueQ();
    issueKV(0, 0);
    if (qt >= 1) issueKV(1, 1);

    if (qt >= 1) cp_wait<1>(); else cp_wait<0>();
    __syncthreads();

    uint32_t qF[16][4];
#pragma unroll
    for (int ks = 0; ks < 16; ks++) {
        const float* ap = Qs + rr0 * QST + (ks << 3) + c;
        qF[ks][0] = __float_as_uint(ap[0]);
        qF[ks][1] = __float_as_uint(ap[8 * QST]);
        qF[ks][2] = __float_as_uint(ap[4]);
        qF[ks][3] = __float_as_uint(ap[8 * QST + 4]);
    }

    float oreg[8][4];
#pragma unroll
    for (int n = 0; n < 8; n++)
#pragma unroll
        for (int r = 0; r < 4; r++) oreg[n][r] = 0.f;

    float m0 = -1e30f, m1 = -1e30f, l0 = 0.f, l1 = 0.f;

    for (int j = 0; j <= qt; j++) {
        if (j > 0) {
            if (j < qt) cp_wait<1>(); else cp_wait<0>();
            __syncthreads();
        }
        const float* Kj = Ks + (j & 1) * K_SZ;
        const float* Vj = Vs + (j & 1) * V_SZ;

        float sacc[4][4];
#pragma unroll
        for (int n = 0; n < 4; n++)
#pragma unroll
            for (int r = 0; r < 4; r++) sacc[n][r] = 0.f;

#pragma unroll
        for (int ks = 0; ks < 16; ks++) {
            const int k0 = ks << 3;
#pragma unroll
            for (int nt = 0; nt < 4; nt++) {
                const float* bp = Kj + (wn * 32 + nt * 8 + g) * KST + k0 + c;
                mma_tf32(sacc[nt], qF[ks][0], qF[ks][1], qF[ks][2], qF[ks][3],
                         __float_as_uint(bp[0]), __float_as_uint(bp[4]));
            }
        }

        if (j == qt) {
#pragma unroll
            for (int nt = 0; nt < 4; nt++) {
                const int cb = wn * 32 + nt * 8 + 2 * c;
                if (cb     > rr0) sacc[nt][0] = -1e30f;
                if (cb + 1 > rr0) sacc[nt][1] = -1e30f;
                if (cb     > rr1) sacc[nt][2] = -1e30f;
                if (cb + 1 > rr1) sacc[nt][3] = -1e30f;
            }
        }

        float rm0 = -1e30f, rm1 = -1e30f;
#pragma unroll
        for (int nt = 0; nt < 4; nt++) {
            rm0 = fmaxf(rm0, fmaxf(sacc[nt][0], sacc[nt][1]));
            rm1 = fmaxf(rm1, fmaxf(sacc[nt][2], sacc[nt][3]));
        }
        rm0 = fmaxf(rm0, __shfl_xor_sync(0xffffffffu, rm0, 1));
        rm0 = fmaxf(rm0, __shfl_xor_sync(0xffffffffu, rm0, 2));
        rm1 = fmaxf(rm1, __shfl_xor_sync(0xffffffffu, rm1, 1));
        rm1 = fmaxf(rm1, __shfl_xor_sync(0xffffffffu, rm1, 2));
        if (c == 0) {
            s_part[wn * 64 + rr0] = rm0;
            s_part[wn * 64 + rr1] = rm1;
        }
        __syncthreads();

        const float t0 = fmaxf(s_part[rr0], s_part[64 + rr0]);
        const float t1 = fmaxf(s_part[rr1], s_part[64 + rr1]);
        const float mn0 = fmaxf(m0, t0), mn1 = fmaxf(m1, t1);
        const float corr0 = __expf(m0 - mn0), corr1 = __expf(m1 - mn1);
        m0 = mn0; m1 = mn1;

        float rs0 = 0.f, rs1 = 0.f;
#pragma unroll
        for (int nt = 0; nt < 4; nt++) {
            const int col = wn * 32 + nt * 8 + 2 * c;
            const float p0 = tf32r(__expf(sacc[nt][0] - mn0));
            const float p1 = tf32r(__expf(sacc[nt][1] - mn0));
            const float p2 = tf32r(__expf(sacc[nt][2] - mn1));
            const float p3 = tf32r(__expf(sacc[nt][3] - mn1));
            rs0 += p0 + p1;
            rs1 += p2 + p3;
            *(float2*)(Ps + rr0 * PST + col) = make_float2(p0, p1);
            *(float2*)(Ps + rr1 * PST + col) = make_float2(p2, p3);
        }
        rs0 += __shfl_xor_sync(0xffffffffu, rs0, 1);
        rs0 += __shfl_xor_sync(0xffffffffu, rs0, 2);
        rs1 += __shfl_xor_sync(0xffffffffu, rs1, 1);
        rs1 += __shfl_xor_sync(0xffffffffu, rs1, 2);
        if (c == 0) {
            s_psum[wn * 64 + rr0] = rs0;
            s_psum[wn * 64 + rr1] = rs1;
        }
        __syncthreads();

        l0 = l0 * corr0 + s_psum[rr0] + s_psum[64 + rr0];
        l1 = l1 * corr1 + s_psum[rr1] + s_psum[64 + rr1];
#pragma unroll
        for (int n = 0; n < 8; n++) {
            oreg[n][0] *= corr0; oreg[n][1] *= corr0;
            oreg[n][2] *= corr1; oreg[n][3] *= corr1;
        }

#pragma unroll
        for (int ks = 0; ks < 8; ks++) {
            const int k0 = ks << 3;
            const float* ap = Ps + rr0 * PST + k0 + c;
            const uint32_t a0 = __float_as_uint(ap[0]);
            const uint32_t a1 = __float_as_uint(ap[8 * PST]);
            const uint32_t a2 = __float_as_uint(ap[4]);
            const uint32_t a3 = __float_as_uint(ap[8 * PST + 4]);
#pragma unroll
            for (int nt = 0; nt < 8; nt++) {
                const float* bp = Vj + (k0 + c) * VST + wn * 64 + nt * 8 + g;
                mma_tf32(oreg[nt], a0, a1, a2, a3,
                         __float_as_uint(bp[0]), __float_as_uint(bp[4 * VST]));
            }
        }
        __syncthreads();

        if (j + 2 <= qt) issueKV(j + 2, j & 1);
    }

    const float inv0 = 1.f / l0;
    const float inv1 = 1.f / l1;
    const int row0 = b * Sn + qb + rr0;
#pragma unroll
    for (int nt = 0; nt < 8; nt++) {
        const int col = h * Dn + wn * 64 + nt * 8 + 2 * c;
        *(float2*)(Og + (size_t)row0 * QDIM + col) =
            make_float2(oreg[nt][0] * inv0, oreg[nt][1] * inv0);
        *(float2*)(Og + (size_t)(row0 + 8) * QDIM + col) =
            make_float2(oreg[nt][2] * inv1, oreg[nt][3] * inv1);
    }
}

// ---------------------------------------------------------------------------
// Launch pipeline
// ---------------------------------------------------------------------------
extern "C" void kernel_launch(void* const* d_in, const int* in_sizes, int n_in,
                              void* d_out, int out_size) {
    const float* x  = (const float*)d_in[0];
    const float* cs = (const float*)d_in[1];
    const float* sn = (const float*)d_in[2];
    const float* Wq = (const float*)d_in[3];
    const float* Wk = (const float*)d_in[4];
    const float* Wv = (const float*)d_in[5];
    const float* Wo = (const float*)d_in[6];
    float* out = (float*)d_out;

    float *Qp, *Kp, *Vp, *Op;
    __half *Xh, *Oh, *Wqt, *Wkt, *Wvt, *Wot;
    cudaGetSymbolAddress((void**)&Qp,  g_Q);
    cudaGetSymbolAddress((void**)&Kp,  g_K);
    cudaGetSymbolAddress((void**)&Vp,  g_V);
    cudaGetSymbolAddress((void**)&Op,  g_O);
    cudaGetSymbolAddress((void**)&Xh,  g_Xh);
    cudaGetSymbolAddress((void**)&Oh,  g_Oh);
    cudaGetSymbolAddress((void**)&Wqt, g_Wqt);
    cudaGetSymbolAddress((void**)&Wkt, g_Wkt);
    cudaGetSymbolAddress((void**)&Wvt, g_Wvt);
    cudaGetSymbolAddress((void**)&Wot, g_Wot);

    cudaFuncSetAttribute(flash_tc_kernel,
                         cudaFuncAttributeMaxDynamicSharedMemorySize, FLASH_SMEM);
    cudaFuncSetAttribute(qkv_hgemm,
                         cudaFuncAttributeMaxDynamicSharedMemorySize, HGEMM_SMEM);
    cudaFuncSetAttribute(wo_hgemm,
                         cudaFuncAttributeMaxDynamicSharedMemorySize, HGEMM_SMEM);

    const int TPB = 256;
    // x -> fp16; weights -> transposed fp16 [N][K]
    f32_to_h_kernel<<<(NTOK * HIDn / 4 + TPB - 1) / TPB, TPB>>>(x, Xh, NTOK * HIDn / 4);
    transpose_h_kernel<<<dim3(QDIM / 32,  HIDn / 32), dim3(32, 8)>>>(Wq, Wqt, HIDn, QDIM);
    transpose_h_kernel<<<dim3(KVDIM / 32, HIDn / 32), dim3(32, 8)>>>(Wk, Wkt, HIDn, KVDIM);
    transpose_h_kernel<<<dim3(KVDIM / 32, HIDn / 32), dim3(32, 8)>>>(Wv, Wvt, HIDn, KVDIM);
    transpose_h_kernel<<<dim3(HIDn / 32,  QDIM / 32), dim3(32, 8)>>>(Wo, Wot, QDIM, HIDn);

    // QKV projections (fp16 mma.sync m16n8k16)
    qkv_hgemm<<<dim3(12, NTOK / 128), 256, HGEMM_SMEM>>>(Xh, Wqt, Wkt, Wvt, Qp, Kp, Vp);

    // RoPE + 1/sqrt(D) fold + tf32 rounding (flash operands)
    rope_round_kernel<<<dim3(NTOK, Hn + Gn + Gn), 64>>>(Qp, Kp, Vp, cs, sn);

    // Flash attention (tf32 mma.sync, parallel register softmax)
    flash_tc_kernel<<<dim3(Sn / BQ, Hn, Bn), 256, FLASH_SMEM>>>(Qp, Kp, Vp, Op);

    // O -> fp16, then output projection (fp16 mma.sync)
    f32_to_h_kernel<<<(NTOK * QDIM / 4 + TPB - 1) / TPB, TPB>>>(Op, Oh, NTOK * QDIM / 4);
    wo_hgemm<<<dim3(HIDn / 256, NTOK / 128), 256, HGEMM_SMEM>>>(Oh, Wot, out);
}

// round 9
// speedup vs baseline: 6.1151x; 1.2838x over previous
#include <cuda_runtime.h>
#include <cuda_fp16.h>
#include <math.h>
#include <stdint.h>

// Problem constants
#define Bn   2
#define Sn   2048
#define HIDn 2048
#define Hn   16
#define Gn   4
#define Dn   128
#define NTOK (Bn * Sn)      // 4096
#define QDIM (Hn * Dn)      // 2048
#define KVDIM (Gn * Dn)     // 512

// Flash tiling
#define BQ 64
#define BK 64

// ---------------------------------------------------------------------------
// Scratch (__device__ globals per allocation-free rule)
// ---------------------------------------------------------------------------
__device__ float  g_Q[NTOK * QDIM];     // fp32 projections (pre-rope)
__device__ float  g_K[NTOK * KVDIM];
__device__ float  g_V[NTOK * KVDIM];
__device__ float  g_O[NTOK * QDIM];
__device__ __half g_Qh[NTOK * QDIM];    // fp16 flash operands
__device__ __half g_Kh[NTOK * KVDIM];
__device__ __half g_Vt[Bn * Gn * Dn * Sn];   // V^T per (b,g): [Dn][Sn]
__device__ __half g_Xh[NTOK * HIDn];
__device__ __half g_Oh[NTOK * QDIM];
__device__ __half g_Wqt[QDIM * HIDn];   // transposed [N][K] fp16
__device__ __half g_Wkt[KVDIM * HIDn];
__device__ __half g_Wvt[KVDIM * HIDn];
__device__ __half g_Wot[HIDn * QDIM];

// ---------------------------------------------------------------------------
// conversion passes
// ---------------------------------------------------------------------------
__global__ void f32_to_h_kernel(const float* __restrict__ in,
                                __half* __restrict__ out, int n4) {
    int i = blockIdx.x * blockDim.x + threadIdx.x;
    if (i < n4) {
        float4 v = ((const float4*)in)[i];
        __half2* o = (__half2*)out + i * 2;
        o[0] = __floats2half2_rn(v.x, v.y);
        o[1] = __floats2half2_rn(v.z, v.w);
    }
}

// Transpose + fp16 convert: in[R][C] fp32 -> out[C][R] fp16
__global__ void transpose_h_kernel(const float* __restrict__ in,
                                   __half* __restrict__ out, int R, int C) {
    __shared__ float t[32][33];
    const int r0 = blockIdx.y * 32, c0 = blockIdx.x * 32;
#pragma unroll
    for (int i = threadIdx.y; i < 32; i += 8)
        t[i][threadIdx.x] = in[(size_t)(r0 + i) * C + c0 + threadIdx.x];
    __syncthreads();
#pragma unroll
    for (int i = threadIdx.y; i < 32; i += 8)
        out[(size_t)(c0 + i) * R + r0 + threadIdx.x] = __float2half_rn(t[threadIdx.x][i]);
}

// Batched V transpose: g_V fp32 [NTOK][KVDIM] -> g_Vt fp16 [(b,g)][Dn][Sn]
// grid (Sn/32, Dn/32, Bn*Gn), block (32,8)
__global__ void vtrans_h_kernel(const float* __restrict__ V, __half* __restrict__ Vt) {
    __shared__ float t[32][33];
    const int s0 = blockIdx.x * 32, d0 = blockIdx.y * 32;
    const int bg = blockIdx.z;
    const int b = bg >> 2, g = bg & 3;
#pragma unroll
    for (int i = threadIdx.y; i < 32; i += 8)
        t[i][threadIdx.x] = V[(size_t)(b * Sn + s0 + i) * KVDIM + g * Dn + d0 + threadIdx.x];
    __syncthreads();
#pragma unroll
    for (int i = threadIdx.y; i < 32; i += 8)
        Vt[((size_t)bg * Dn + d0 + i) * Sn + s0 + threadIdx.x] =
            __float2half_rn(t[threadIdx.x][i]);
}

// ---------------------------------------------------------------------------
// cp.async helpers
// ---------------------------------------------------------------------------
__device__ __forceinline__ void cp_async16(uint32_t dst, const void* src) {
    asm volatile("cp.async.cg.shared.global [%0], [%1], 16;" :: "r"(dst), "l"(src));
}
__device__ __forceinline__ void cp_commit() {
    asm volatile("cp.async.commit_group;");
}
template <int N>
__device__ __forceinline__ void cp_wait() {
    asm volatile("cp.async.wait_group %0;" :: "n"(N));
}

// ---------------------------------------------------------------------------
// fp16 mma helper
// ---------------------------------------------------------------------------
__device__ __forceinline__
void mma_f16(float* d, uint32_t a0, uint32_t a1, uint32_t a2, uint32_t a3,
             uint32_t b0, uint32_t b1) {
    asm volatile(
        "mma.sync.aligned.m16n8k16.row.col.f32.f16.f16.f32 "
        "{%0,%1,%2,%3}, {%4,%5,%6,%7}, {%8,%9}, {%0,%1,%2,%3};"
        : "+f"(d[0]), "+f"(d[1]), "+f"(d[2]), "+f"(d[3])
        : "r"(a0), "r"(a1), "r"(a2), "r"(a3), "r"(b0), "r"(b1));
}

// ---------------------------------------------------------------------------
// fp16 mma.sync GEMM (unchanged from passing R8): C[fp32] = A(h) @ Bt(h)^T
// ---------------------------------------------------------------------------
#define HA_ST 72
#define HA_SZ (128 * HA_ST)
#define HB_SZ (256 * HA_ST)
#define HSTG_B ((HA_SZ + HB_SZ) * 2)    // 55296 B
#define HNSTG 3
#define HGEMM_SMEM (HNSTG * HSTG_B)     // 165888 B

__device__ __forceinline__
void hgemm_body(const __half* __restrict__ A, const __half* __restrict__ Bt,
                float* __restrict__ C, int Ncols, int colbase, int K, int by) {
    extern __shared__ char hsm[];
    const int tid  = threadIdx.x;
    const int w    = tid >> 5, lane = tid & 31;
    const int wm   = w >> 2,   wn   = w & 3;
    const int g    = lane >> 2, c   = lane & 3;

    const uint32_t smbase = (uint32_t)__cvta_generic_to_shared(hsm);

    float d[4][8][4];
#pragma unroll
    for (int i = 0; i < 4; i++)
#pragma unroll
        for (int j = 0; j < 8; j++)
#pragma unroll
            for (int r = 0; r < 4; r++) d[i][j][r] = 0.f;

    const int niter = K / 64;
    const __half* Abase = A + (size_t)(by * 128) * K;
    const __half* Bbase = Bt + (size_t)colbase * K;

    auto issue = [&](int it) {
        const int s = it % HNSTG;
        const uint32_t aB = smbase + (uint32_t)(s * HSTG_B);
        const uint32_t bB = aB + (uint32_t)(HA_SZ * 2);
        const __half* Ag = Abase + it * 64;
        const __half* Bg = Bbase + it * 64;
#pragma unroll
        for (int i = 0; i < 4; i++) {
            const int f = i * 256 + tid;
            const int row = f >> 3;
            const int u = ((f & 7) + row) & 7;
            cp_async16(aB + (uint32_t)(row * 144 + u * 16),
                       Ag + (size_t)row * K + u * 8);
        }
#pragma unroll
        for (int i = 0; i < 8; i++) {
            const int f = i * 256 + tid;
            const int row = f >> 3;
            const int u = ((f & 7) + row) & 7;
            cp_async16(bB + (uint32_t)(row * 144 + u * 16),
                       Bg + (size_t)row * K + u * 8);
        }
        cp_commit();
    };

    issue(0); issue(1); issue(2);

    for (int it = 0; it < niter; it++) {
        cp_wait<HNSTG - 1>();
        __syncthreads();

        const __half* sA = (const __half*)(hsm + (it % HNSTG) * HSTG_B);
        const __half* sB = sA + HA_SZ;

#pragma unroll
        for (int s = 0; s < 4; s++) {
            const int kh = s * 16 + 2 * c;
            uint32_t aF[4][4], bF[8][2];
#pragma unroll
            for (int i = 0; i < 4; i++) {
                const __half* ap = sA + (wm * 64 + i * 16 + g) * HA_ST + kh;
                aF[i][0] = *(const uint32_t*)(ap);
                aF[i][1] = *(const uint32_t*)(ap + 8 * HA_ST);
                aF[i][2] = *(const uint32_t*)(ap + 8);
                aF[i][3] = *(const uint32_t*)(ap + 8 * HA_ST + 8);
            }
#pragma unroll
            for (int j = 0; j < 8; j++) {
                const __half* bp = sB + (wn * 64 + j * 8 + g) * HA_ST + kh;
                bF[j][0] = *(const uint32_t*)(bp);
                bF[j][1] = *(const uint32_t*)(bp + 8);
            }
#pragma unroll
            for (int i = 0; i < 4; i++)
#pragma unroll
                for (int j = 0; j < 8; j++)
                    mma_f16(d[i][j], aF[i][0], aF[i][1], aF[i][2], aF[i][3],
                            bF[j][0], bF[j][1]);
        }
        __syncthreads();
        if (it + HNSTG < niter) issue(it + HNSTG);
    }

#pragma unroll
    for (int i = 0; i < 4; i++) {
        const int r0 = by * 128 + wm * 64 + i * 16 + g;
#pragma unroll
        for (int j = 0; j < 8; j++) {
            const int col = colbase + wn * 64 + j * 8 + c * 2;
            *(float2*)(C + (size_t)r0 * Ncols + col)       = make_float2(d[i][j][0], d[i][j][1]);
            *(float2*)(C + (size_t)(r0 + 8) * Ncols + col) = make_float2(d[i][j][2], d[i][j][3]);
        }
    }
}

__global__ __launch_bounds__(256, 1)
void qkv_hgemm(const __half* __restrict__ x,
               const __half* __restrict__ Wqt, const __half* __restrict__ Wkt,
               const __half* __restrict__ Wvt,
               float* __restrict__ Q, float* __restrict__ K, float* __restrict__ V) {
    const int bx = blockIdx.x;
    const __half* Bt; float* C; int Ncols; int cx;
    if (bx < 8)       { Bt = Wqt; C = Q; Ncols = QDIM;  cx = bx; }
    else if (bx < 10) { Bt = Wkt; C = K; Ncols = KVDIM; cx = bx - 8; }
    else              { Bt = Wvt; C = V; Ncols = KVDIM; cx = bx - 10; }
    hgemm_body(x, Bt, C, Ncols, cx * 256, HIDn, blockIdx.y);
}

__global__ __launch_bounds__(256, 1)
void wo_hgemm(const __half* __restrict__ A, const __half* __restrict__ Bt,
              float* __restrict__ C) {
    hgemm_body(A, Bt, C, HIDn, blockIdx.x * 256, QDIM, blockIdx.y);
}

// ---------------------------------------------------------------------------
// RoPE: fp32 Q/K in -> fp16 Q/K out (Q pre-scaled by 1/sqrt(D))
// grid (NTOK, Hn+Gn), 64 threads
// ---------------------------------------------------------------------------
__global__ void rope_h_kernel(const float* __restrict__ Q, const float* __restrict__ K,
                              __half* __restrict__ Qh, __half* __restrict__ Kh,
                              const float* __restrict__ cs, const float* __restrict__ sn) {
    const int t = blockIdx.x;
    const int h = blockIdx.y;
    const int d = threadIdx.x;        // 0..63
    const int s = t & (Sn - 1);
    const float c1 = cs[s * Dn + d],      s1 = sn[s * Dn + d];
    const float c2 = cs[s * Dn + d + 64], s2 = sn[s * Dn + d + 64];
    const bool isQ = (h < Hn);
    const float sc = isQ ? 0.08838834764831845f : 1.0f;   // 1/sqrt(128)
    const float* p = isQ ? (Q + (size_t)t * QDIM + h * Dn)
                         : (K + (size_t)t * KVDIM + (h - Hn) * Dn);
    __half* o = isQ ? (Qh + (size_t)t * QDIM + h * Dn)
                    : (Kh + (size_t)t * KVDIM + (h - Hn) * Dn);
    const float a = p[d], b = p[d + 64];
    o[d]      = __float2half_rn((a * c1 - b * s1) * sc);
    o[d + 64] = __float2half_rn((b * c2 + a * s2) * sc);
}

// ---------------------------------------------------------------------------
// Causal GQA flash attention, fp16 m16n8k16, parallel register softmax.
// BQ=64, BK=64, D=128. Q/K smem [64][136]h (68 words ≡ 4 mod 32 — banks
// 4g+c distinct), V^T smem [128][72]h, P [64][72]h aliasing Q. K/V 2-stage
// cp.async. Q fragments hoisted (32 regs). O accum fp32 in regs.
// ---------------------------------------------------------------------------
#define QH_ST 136
#define VH_ST 72
#define PH_ST 72
#define QH_SZ (BQ * QH_ST)              // 8704 halves
#define KH_SZ (BK * QH_ST)              // 8704
#define VH_SZ (Dn * VH_ST)              // 9216
#define FPART_OFF (QH_SZ + 2 * KH_SZ + 2 * VH_SZ)   // halves = 44544
#define FLASH_SMEM (FPART_OFF * 2 + 256 * 4)        // 90112 B

__global__ __launch_bounds__(256)
void flash_h_kernel(const __half* __restrict__ Qg, const __half* __restrict__ Kg,
                    const __half* __restrict__ Vtg, float* __restrict__ Og) {
    extern __shared__ __half smh[];
    __half* Qs = smh;                         // [64][136]
    __half* Ps = smh;                         // [64][72] aliases Qs
    __half* Ks = smh + QH_SZ;                 // 2 x [64][136]
    __half* Vs = smh + QH_SZ + 2 * KH_SZ;     // 2 x [128][72]
    float* s_part = (float*)(smh + FPART_OFF);   // [2][64]
    float* s_psum = s_part + 128;                // [2][64]
    const uint32_t smbase = (uint32_t)__cvta_generic_to_shared(smh);

    const int tid = threadIdx.x;
    const int w = tid >> 5, lane = tid & 31;
    const int g = lane >> 2, c = lane & 3;
    const int wm = w & 3;                     // row tile
    const int wn = w >> 2;                    // col half

    const int h = blockIdx.y;
    const int b = blockIdx.z;
    const int qt = (int)gridDim.x - 1 - (int)blockIdx.x;
    const int qb = qt * BQ;
    const int gh = h >> 2;

    const int rr0 = wm * 16 + g;
    const int rr1 = rr0 + 8;

    auto issueQ = [&]() {
        const __half* src = Qg + ((size_t)(b * Sn + qb)) * QDIM + h * Dn;
#pragma unroll
        for (int i = 0; i < 4; i++) {         // 1024 16B units
            const int f = i * 256 + tid;
            const int r = f >> 4, u = f & 15;
            cp_async16(smbase + (uint32_t)(r * (QH_ST * 2) + u * 16),
                       src + (size_t)r * QDIM + u * 8);
        }
    };
    auto issueKV = [&](int j, int s) {
        const __half* ksrc = Kg + ((size_t)(b * Sn + j * BK)) * KVDIM + gh * Dn;
        const __half* vsrc = Vtg + ((size_t)(b * Gn + gh) * Dn) * Sn + j * BK;
        const uint32_t kb = smbase + (uint32_t)(QH_SZ + s * KH_SZ) * 2u;
        const uint32_t vb = smbase + (uint32_t)(QH_SZ + 2 * KH_SZ + s * VH_SZ) * 2u;
#pragma unroll
        for (int i = 0; i < 4; i++) {         // K: 1024 units
            const int f = i * 256 + tid;
            const int r = f >> 4, u = f & 15;
            cp_async16(kb + (uint32_t)(r * (QH_ST * 2) + u * 16),
                       ksrc + (size_t)r * KVDIM + u * 8);
        }
#pragma unroll
        for (int i = 0; i < 4; i++) {         // V^T: 1024 units (128 rows x 8)
            const int f = i * 256 + tid;
            const int r = f >> 3, u = f & 7;
            cp_async16(vb + (uint32_t)(r * (VH_ST * 2) + u * 16),
                       vsrc + (size_t)r * Sn + u * 8);
        }
        cp_commit();
    };

    issueQ();
    issueKV(0, 0);
    if (qt >= 1) issueKV(1, 1);

    if (qt >= 1) cp_wait<1>(); else cp_wait<0>();
    __syncthreads();

    // hoist Q fragments (8 k16-steps x 4 regs)
    uint32_t qF[8][4];
#pragma unroll
    for (int ks = 0; ks < 8; ks++) {
        const __half* ap = Qs + rr0 * QH_ST + ks * 16 + 2 * c;
        qF[ks][0] = *(const uint32_t*)(ap);
        qF[ks][1] = *(const uint32_t*)(ap + 8 * QH_ST);
        qF[ks][2] = *(const uint32_t*)(ap + 8);
        qF[ks][3] = *(const uint32_t*)(ap + 8 * QH_ST + 8);
    }

    float oreg[8][4];
#pragma unroll
    for (int n = 0; n < 8; n++)
#pragma unroll
        for (int r = 0; r < 4; r++) oreg[n][r] = 0.f;

    float m0 = -1e30f, m1 = -1e30f, l0 = 0.f, l1 = 0.f;

    for (int j = 0; j <= qt; j++) {
        if (j > 0) {
            if (j < qt) cp_wait<1>(); else cp_wait<0>();
            __syncthreads();
        }
        const __half* Kj = Ks + (j & 1) * KH_SZ;
        const __half* Vj = Vs + (j & 1) * VH_SZ;

        // ---- S = Q K^T ----
        float sacc[4][4];
#pragma unroll
        for (int n = 0; n < 4; n++)
#pragma unroll
            for (int r = 0; r < 4; r++) sacc[n][r] = 0.f;

#pragma unroll
        for (int ks = 0; ks < 8; ks++) {
            const int kh = ks * 16 + 2 * c;
#pragma unroll
            for (int nt = 0; nt < 4; nt++) {
                const __half* bp = Kj + (wn * 32 + nt * 8 + g) * QH_ST + kh;
                mma_f16(sacc[nt], qF[ks][0], qF[ks][1], qF[ks][2], qF[ks][3],
                        *(const uint32_t*)(bp), *(const uint32_t*)(bp + 8));
            }
        }

        // ---- causal mask (diagonal tile) ----
        if (j == qt) {
#pragma unroll
            for (int nt = 0; nt < 4; nt++) {
                const int cb = wn * 32 + nt * 8 + 2 * c;
                if (cb     > rr0) sacc[nt][0] = -1e30f;
                if (cb + 1 > rr0) sacc[nt][1] = -1e30f;
                if (cb     > rr1) sacc[nt][2] = -1e30f;
                if (cb + 1 > rr1) sacc[nt][3] = -1e30f;
            }
        }

        // ---- row max ----
        float rm0 = -1e30f, rm1 = -1e30f;
#pragma unroll
        for (int nt = 0; nt < 4; nt++) {
            rm0 = fmaxf(rm0, fmaxf(sacc[nt][0], sacc[nt][1]));
            rm1 = fmaxf(rm1, fmaxf(sacc[nt][2], sacc[nt][3]));
        }
        rm0 = fmaxf(rm0, __shfl_xor_sync(0xffffffffu, rm0, 1));
        rm0 = fmaxf(rm0, __shfl_xor_sync(0xffffffffu, rm0, 2));
        rm1 = fmaxf(rm1, __shfl_xor_sync(0xffffffffu, rm1, 1));
        rm1 = fmaxf(rm1, __shfl_xor_sync(0xffffffffu, rm1, 2));
        if (c == 0) {
            s_part[wn * 64 + rr0] = rm0;
            s_part[wn * 64 + rr1] = rm1;
        }
        __syncthreads();

        const float t0 = fmaxf(s_part[rr0], s_part[64 + rr0]);
        const float t1 = fmaxf(s_part[rr1], s_part[64 + rr1]);
        const float mn0 = fmaxf(m0, t0), mn1 = fmaxf(m1, t1);
        const float corr0 = __expf(m0 - mn0), corr1 = __expf(m1 - mn1);
        m0 = mn0; m1 = mn1;

        // ---- exp + fp16 P + row sums ----
        float rs0 = 0.f, rs1 = 0.f;
#pragma unroll
        for (int nt = 0; nt < 4; nt++) {
            const int col = wn * 32 + nt * 8 + 2 * c;
            const float p0 = __expf(sacc[nt][0] - mn0);
            const float p1 = __expf(sacc[nt][1] - mn0);
            const float p2 = __expf(sacc[nt][2] - mn1);
            const float p3 = __expf(sacc[nt][3] - mn1);
            rs0 += p0 + p1;
            rs1 += p2 + p3;
            *(__half2*)(Ps + rr0 * PH_ST + col) = __floats2half2_rn(p0, p1);
            *(__half2*)(Ps + rr1 * PH_ST + col) = __floats2half2_rn(p2, p3);
        }
        rs0 += __shfl_xor_sync(0xffffffffu, rs0, 1);
        rs0 += __shfl_xor_sync(0xffffffffu, rs0, 2);
        rs1 += __shfl_xor_sync(0xffffffffu, rs1, 1);
        rs1 += __shfl_xor_sync(0xffffffffu, rs1, 2);
        if (c == 0) {
            s_psum[wn * 64 + rr0] = rs0;
            s_psum[wn * 64 + rr1] = rs1;
        }
        __syncthreads();

        l0 = l0 * corr0 + s_psum[rr0] + s_psum[64 + rr0];
        l1 = l1 * corr1 + s_psum[rr1] + s_psum[64 + rr1];
#pragma unroll
        for (int n = 0; n < 8; n++) {
            oreg[n][0] *= corr0; oreg[n][1] *= corr0;
            oreg[n][2] *= corr1; oreg[n][3] *= corr1;
        }

        // ---- O += P @ V : A = P [64 x 64], B = V^T smem [d][seq] ----
#pragma unroll
        for (int s = 0; s < 4; s++) {
            const int kh = s * 16 + 2 * c;
            const __half* ap = Ps + rr0 * PH_ST + kh;
            const uint32_t a0 = *(const uint32_t*)(ap);
            const uint32_t a1 = *(const uint32_t*)(ap + 8 * PH_ST);
            const uint32_t a2 = *(const uint32_t*)(ap + 8);
            const uint32_t a3 = *(const uint32_t*)(ap + 8 * PH_ST + 8);
#pragma unroll
            for (int nt = 0; nt < 8; nt++) {
                const __half* bp = Vj + (wn * 64 + nt * 8 + g) * VH_ST + kh;
                mma_f16(oreg[nt], a0, a1, a2, a3,
                        *(const uint32_t*)(bp), *(const uint32_t*)(bp + 8));
            }
        }
        __syncthreads();

        if (j + 2 <= qt) issueKV(j + 2, j & 1);
    }

    const float inv0 = 1.f / l0;
    const float inv1 = 1.f / l1;
    const int row0 = b * Sn + qb + rr0;
#pragma unroll
    for (int nt = 0; nt < 8; nt++) {
        const int col = h * Dn + wn * 64 + nt * 8 + 2 * c;
        *(float2*)(Og + (size_t)row0 * QDIM + col) =
            make_float2(oreg[nt][0] * inv0, oreg[nt][1] * inv0);
        *(float2*)(Og + (size_t)(row0 + 8) * QDIM + col) =
            make_float2(oreg[nt][2] * inv1, oreg[nt][3] * inv1);
    }
}

// ---------------------------------------------------------------------------
// Launch pipeline
// ---------------------------------------------------------------------------
extern "C" void kernel_launch(void* const* d_in, const int* in_sizes, int n_in,
                              void* d_out, int out_size) {
    const float* x  = (const float*)d_in[0];
    const float* cs = (const float*)d_in[1];
    const float* sn = (const float*)d_in[2];
    const float* Wq = (const float*)d_in[3];
    const float* Wk = (const float*)d_in[4];
    const float* Wv = (const float*)d_in[5];
    const float* Wo = (const float*)d_in[6];
    float* out = (float*)d_out;

    float *Qp, *Kp, *Vp, *Op;
    __half *Qh, *Kh, *Vt, *Xh, *Oh, *Wqt, *Wkt, *Wvt, *Wot;
    cudaGetSymbolAddress((void**)&Qp,  g_Q);
    cudaGetSymbolAddress((void**)&Kp,  g_K);
    cudaGetSymbolAddress((void**)&Vp,  g_V);
    cudaGetSymbolAddress((void**)&Op,  g_O);
    cudaGetSymbolAddress((void**)&Qh,  g_Qh);
    cudaGetSymbolAddress((void**)&Kh,  g_Kh);
    cudaGetSymbolAddress((void**)&Vt,  g_Vt);
    cudaGetSymbolAddress((void**)&Xh,  g_Xh);
    cudaGetSymbolAddress((void**)&Oh,  g_Oh);
    cudaGetSymbolAddress((void**)&Wqt, g_Wqt);
    cudaGetSymbolAddress((void**)&Wkt, g_Wkt);
    cudaGetSymbolAddress((void**)&Wvt, g_Wvt);
    cudaGetSymbolAddress((void**)&Wot, g_Wot);

    cudaFuncSetAttribute(flash_h_kernel,
                         cudaFuncAttributeMaxDynamicSharedMemorySize, FLASH_SMEM);
    cudaFuncSetAttribute(qkv_hgemm,
                         cudaFuncAttributeMaxDynamicSharedMemorySize, HGEMM_SMEM);
    cudaFuncSetAttribute(wo_hgemm,
                         cudaFuncAttributeMaxDynamicSharedMemorySize, HGEMM_SMEM);

    const int TPB = 256;
    // x -> fp16; weights -> transposed fp16 [N][K]
    f32_to_h_kernel<<<(NTOK * HIDn / 4 + TPB - 1) / TPB, TPB>>>(x, Xh, NTOK * HIDn / 4);
    transpose_h_kernel<<<dim3(QDIM / 32,  HIDn / 32), dim3(32, 8)>>>(Wq, Wqt, HIDn, QDIM);
    transpose_h_kernel<<<dim3(KVDIM / 32, HIDn / 32), dim3(32, 8)>>>(Wk, Wkt, HIDn, KVDIM);
    transpose_h_kernel<<<dim3(KVDIM / 32, HIDn / 32), dim3(32, 8)>>>(Wv, Wvt, HIDn, KVDIM);
    transpose_h_kernel<<<dim3(HIDn / 32,  QDIM / 32), dim3(32, 8)>>>(Wo, Wot, QDIM, HIDn);

    // QKV projections (fp16 mma.sync)
    qkv_hgemm<<<dim3(12, NTOK / 128), 256, HGEMM_SMEM>>>(Xh, Wqt, Wkt, Wvt, Qp, Kp, Vp);

    // RoPE -> fp16 Q/K; V -> transposed fp16
    rope_h_kernel<<<dim3(NTOK, Hn + Gn), 64>>>(Qp, Kp, Qh, Kh, cs, sn);
    vtrans_h_kernel<<<dim3(Sn / 32, Dn / 32, Bn * Gn), dim3(32, 8)>>>(Vp, Vt);

    // Flash attention (fp16 mma.sync)
    flash_h_kernel<<<dim3(Sn / BQ, Hn, Bn), 256, FLASH_SMEM>>>(Qh, Kh, Vt, Op);

    // O -> fp16, then output projection
    f32_to_h_kernel<<<(NTOK * QDIM / 4 + TPB - 1) / TPB, TPB>>>(Op, Oh, NTOK * QDIM / 4);
    wo_hgemm<<<dim3(HIDn / 256, NTOK / 128), 256, HGEMM_SMEM>>>(Oh, Wot, out);
}